// round 6
// baseline (speedup 1.0000x reference)
#include <cuda_runtime.h>
#include <cuda_fp16.h>
#include <cstdint>
#include <cstddef>

// ---------------------------------------------------------------- constants
#define BB    512
#define LL    200
#define DIMN  256
#define KCODE 2048
#define NROWS (BB * LL)          // 102400
#define VOCAB 100000

#define MT    128                // unique ids per CTA
#define NTIL  64                 // codes per tile
#define NT    (KCODE / NTIL)     // 32 tiles
#define TILE_BYTES 32768         // 64 codes * 256 dims * 2B fp16
#define TAU   4e-3f              // rescore window (~10 sigma of fp16 dist error)
#define MAXCTA ((VOCAB + MT - 1) / MT)   // 782
#define FB    4                  // batches per finish CTA

// smem layout (argmin kernel)
#define SO_BAR  0                // mbarriers: bfull[2]@0,8  cons[2]@16,24
#define SO_MAP  64               // 128 ints (unique-id slice)
#define SO_CN   1024             // 8KB cnorm
#define SO_B    9216             // 2 x 32KB B tile buffers (1KB aligned)
#define SMEM_TOTAL (SO_B + 2 * TILE_BYTES)   // 74752

__device__ float  g_cnorm[KCODE];
__device__ int    g_mark[VOCAB];
__device__ int    g_uniq[VOCAB];
__device__ int    g_nuniq;
__device__ int    g_c0;
__device__ int    g_ridx[VOCAB];         // per-id argmin result
__device__ float2 g_rmeta[VOCAB];
__device__ int4   g_rcand[VOCAB];
__device__ __align__(16) unsigned char g_btiles[NT * TILE_BYTES];  // 1MB fp16 pre-swizzled

// ---------------------------------------------------------------- PTX helpers
__device__ __forceinline__ uint32_t smem_u32(const void* p) {
    uint32_t a;
    asm("{ .reg .u64 t; cvta.to.shared.u64 t, %1; cvt.u32.u64 %0, t; }" : "=r"(a) : "l"(p));
    return a;
}
#define MBAR_INIT(a, n) asm volatile("mbarrier.init.shared.b64 [%0], %1;" :: "r"(a), "r"(n) : "memory")
#define MBAR_EXPECT_TX(a, b) asm volatile("mbarrier.arrive.expect_tx.shared.b64 _, [%0], %1;" :: "r"(a), "r"(b) : "memory")
#define MBAR_ARRIVE(a) asm volatile("mbarrier.arrive.shared.b64 _, [%0];" :: "r"(a) : "memory")
#define MBAR_WAIT(a, p) do {                                                   \
    asm volatile("{\n\t.reg .pred P1;\n\tWL%=:\n\t"                            \
        "mbarrier.try_wait.parity.acquire.cta.shared::cta.b64 P1, [%0], %1, 0x989680;\n\t" \
        "@P1 bra.uni WD%=;\n\tbra.uni WL%=;\n\tWD%=:\n\t}"                     \
        :: "r"(a), "r"(p) : "memory");                                         \
} while (0)
#define BULK_G2S(dst, src, bytes, mbar)                                        \
    asm volatile("cp.async.bulk.shared::cta.global.mbarrier::complete_tx::bytes [%0], [%1], %2, [%3];" \
                 :: "r"(dst), "l"(src), "r"(bytes), "r"(mbar) : "memory")

#define LDSM_X4(r, a)                                                          \
    asm volatile("ldmatrix.sync.aligned.m8n8.x4.shared.b16 {%0,%1,%2,%3}, [%4];" \
        : "=r"((r)[0]), "=r"((r)[1]), "=r"((r)[2]), "=r"((r)[3]) : "r"(a))

__device__ __forceinline__ void mma_f16(float* d, const unsigned* a, const unsigned* b) {
    asm volatile("mma.sync.aligned.m16n8k16.row.col.f32.f16.f16.f32 "
        "{%0,%1,%2,%3}, {%4,%5,%6,%7}, {%8,%9}, {%0,%1,%2,%3};"
        : "+f"(d[0]), "+f"(d[1]), "+f"(d[2]), "+f"(d[3])
        : "r"(a[0]), "r"(a[1]), "r"(a[2]), "r"(a[3]), "r"(b[0]), "r"(b[1]));
}
__device__ __forceinline__ unsigned packh(float a, float b) {
    __half2 h = __floats2half2_rn(a, b);
    return *reinterpret_cast<unsigned*>(&h);
}
// lexicographic sorted-insert into ascending top-4
__device__ __forceinline__ void ins4(float d, int c, float v[4], int ix[4]) {
#pragma unroll
    for (int q = 0; q < 4; q++) {
        bool lt = (d < v[q]) || (d == v[q] && c < ix[q]);
        float tv = lt ? d : v[q];  int ti = lt ? c : ix[q];
        float nd = lt ? v[q] : d;  int nc = lt ? ix[q] : c;
        v[q] = tv; ix[q] = ti; d = nd; c = nc;
    }
}

// ---------------------------------------------------------------- kernel 1: ||c||^2
__global__ void cnorm_kernel(const float* __restrict__ cb) {
    int code = blockIdx.x * 8 + (threadIdx.x >> 5);
    int lane = threadIdx.x & 31;
    const float4* p = (const float4*)(cb + (size_t)code * DIMN);
    float s = 0.f;
#pragma unroll
    for (int i = 0; i < 2; i++) {
        float4 v = p[lane + 32 * i];
        s += v.x * v.x + v.y * v.y + v.z * v.z + v.w * v.w;
    }
#pragma unroll
    for (int o = 16; o; o >>= 1) s += __shfl_xor_sync(0xffffffffu, s, o);
    if (lane == 0) g_cnorm[code] = s;
}

// ---------------------------------------------------------------- kernel 2: fp16 codebook tiles
// (also zeroes the dedup mark array + counter). code n at n*512 + (d*2 ^ ((n&7)<<4))
__global__ void bsplit_kernel(const float* __restrict__ cb) {
    int idx = blockIdx.x * blockDim.x + threadIdx.x;   // 0 .. 262143
    if (idx < VOCAB) g_mark[idx] = 0;
    if (idx == 0) g_nuniq = 0;
    int k  = idx >> 7;          // code
    int dp = idx & 127;         // dim pair
    float c0 = cb[(size_t)k * DIMN + 2 * dp];
    float c1 = cb[(size_t)k * DIMN + 2 * dp + 1];
    int tile = k >> 6, n = k & 63;
    uint32_t byte = (uint32_t)n * 512u + (uint32_t)dp * 4u;
    byte ^= (uint32_t)(n & 7) << 4;
    *(unsigned*)(g_btiles + (uint32_t)tile * TILE_BYTES + byte) = packh(c0, c1);
}

// ---------------------------------------------------------------- kernel 3: collect unique valid ids
__global__ void compact_kernel(const int* __restrict__ ids, const int* __restrict__ msk) {
    int r = blockIdx.x * blockDim.x + threadIdx.x;
    if (r >= NROWS) return;
    if (msk[r] >= 1) {
        int id = ids[r];
        if (atomicExch(&g_mark[id], 1) == 0) {
            int pos = atomicAdd(&g_nuniq, 1);
            g_uniq[pos] = id;
        }
    }
}

// ---------------------------------------------------------------- kernel 4: fp16 HMMA argmin (unique ids)
// Decoupled warps: per-buffer consumption mbarriers instead of per-tile CTA barriers.
__global__ void __launch_bounds__(256, 2)
argmin_mma(const float* __restrict__ emb)
{
    extern __shared__ char smem[];
    const uint32_t sb  = smem_u32(smem);
    const int tid = threadIdx.x;
    const int l   = tid & 31;
    const int w   = tid >> 5;
    const int r0  = blockIdx.x * MT;
    const int nuniq = g_nuniq;
    if (r0 >= nuniq) return;                    // whole-CTA early exit
    float* s_cn  = (float*)(smem + SO_CN);
    int*   s_map = (int*)(smem + SO_MAP);

    const uint32_t mb_bfull = sb + SO_BAR;        // +8*buf
    const uint32_t mb_cons  = sb + SO_BAR + 16;   // +8*buf

    if (tid == 0) {
        MBAR_INIT(mb_bfull + 0, 1); MBAR_INIT(mb_bfull + 8, 1);
        MBAR_INIT(mb_cons + 0, 8);  MBAR_INIT(mb_cons + 8, 8);
    }

    // ---- stage A rows (fp16) into the B-buffer region temporarily
    {
        const int row  = tid >> 1, half = tid & 1;
        int u = r0 + row; if (u >= nuniq) u = nuniq - 1;   // tail duplicates
        const int id = g_uniq[u];
        if (half == 0) s_map[row] = id;
        const float4* ep = (const float4*)(emb + (size_t)id * DIMN + half * 128);
        const uint32_t rowbase = (uint32_t)row * 512u;
        const uint32_t hb = (uint32_t)half * 256u;
        const uint32_t xo = (uint32_t)(row & 7) << 4;
#pragma unroll
        for (int q = 0; q < 32; q++) {
            float4 v = ep[q];
            uint32_t off = rowbase + ((hb + (uint32_t)q * 8u) ^ xo);
            *(unsigned*)(smem + SO_B + off)     = packh(v.x, v.y);
            *(unsigned*)(smem + SO_B + off + 4) = packh(v.z, v.w);
        }
        for (int i = tid; i < KCODE; i += 256) s_cn[i] = g_cnorm[i];
    }
    __syncthreads();

    // ---- fragment address constants
    const uint32_t xorv   = (uint32_t)(l & 7) << 4;
    const uint32_t arow   = (uint32_t)(w * 16 + (l & 7) + ((l >> 3) & 1) * 8);
    const uint32_t koff_a = (uint32_t)((l >> 4) & 1) * 16u;
    const uint32_t jpoff  = (uint32_t)((l >> 4) & 1) * 4096u + (uint32_t)(l & 7) * 512u;
    const uint32_t koff_b = (uint32_t)((l >> 3) & 1) * 16u;

    // ---- A fragments -> persistent registers (64 regs)
    unsigned ah[16][4];
    {
        const uint32_t a_b = sb + SO_B + arow * 512u;
#pragma unroll
        for (int s = 0; s < 16; s++)
            LDSM_X4(ah[s], a_b + (((uint32_t)(s * 32) + koff_a) ^ xorv));
    }
    __syncthreads();   // staging free -> becomes B double buffer

    if (tid == 0) {
        MBAR_EXPECT_TX(mb_bfull + 0, TILE_BYTES);
        BULK_G2S(sb + SO_B, (const void*)g_btiles, TILE_BYTES, mb_bfull + 0);
        MBAR_EXPECT_TX(mb_bfull + 8, TILE_BYTES);
        BULK_G2S(sb + SO_B + TILE_BYTES, (const void*)(g_btiles + TILE_BYTES),
                 TILE_BYTES, mb_bfull + 8);
    }

    float acc[8][4];
#pragma unroll
    for (int j = 0; j < 8; j++)
#pragma unroll
        for (int e = 0; e < 4; e++) acc[j][e] = 0.f;

    float v4[2][4]; int ix4[2][4];
#pragma unroll
    for (int rr = 0; rr < 2; rr++)
#pragma unroll
        for (int q = 0; q < 4; q++) { v4[rr][q] = 3.4e38f; ix4[rr][q] = 0x7fffffff; }

    int bpar[2] = {0, 0};       // bfull parity (per warp)
    int cpar[2] = {0, 0};       // cons parity (producer only)

    for (int t = 0; t < NT; t++) {
        const int buf = t & 1;
        const uint32_t Bb = sb + SO_B + (uint32_t)buf * TILE_BYTES;
        MBAR_WAIT(mb_bfull + 8 * buf, (uint32_t)bpar[buf]); bpar[buf] ^= 1;

        // flat (s,p) loop with software-pipelined B loads (2-deep reg buffer)
        unsigned b4[2][4];
        LDSM_X4(b4[0], Bb + jpoff + (koff_b ^ xorv));
#pragma unroll
        for (int idx = 0; idx < 64; idx++) {
            const int s = idx >> 2, p = idx & 3, cur = idx & 1;
            if (idx < 63) {
                const int ns = (idx + 1) >> 2, np = (idx + 1) & 3;
                const uint32_t kxn = ((uint32_t)(ns * 32) + koff_b) ^ xorv;
                LDSM_X4(b4[cur ^ 1], Bb + jpoff + (uint32_t)np * 8192u + kxn);
            }
            mma_f16(acc[2 * p],     ah[s], b4[cur]);
            mma_f16(acc[2 * p + 1], ah[s], b4[cur] + 2);
        }
        if (l == 0) MBAR_ARRIVE(mb_cons + 8 * buf);   // this warp done reading buf

        // epilogue: dist = ||c||^2 - 2*acc; top-4 per row (guarded insert)
        const int cbase = t * NTIL;
#pragma unroll
        for (int j = 0; j < 8; j++) {
#pragma unroll
            for (int e = 0; e < 4; e++) {
                const int rr   = e >> 1;
                const int code = cbase + j * 8 + 2 * (l & 3) + (e & 1);
                const float dist = fmaf(-2.0f, acc[j][e], s_cn[code]);
                if (dist < v4[rr][3]) ins4(dist, code, v4[rr], ix4[rr]);
                acc[j][e] = 0.f;
            }
        }

        if (tid == 0 && t + 2 < NT) {   // refill after all 8 warps consumed buf
            MBAR_WAIT(mb_cons + 8 * buf, (uint32_t)cpar[buf]); cpar[buf] ^= 1;
            MBAR_EXPECT_TX(mb_bfull + 8 * buf, TILE_BYTES);
            BULK_G2S(Bb, (const void*)(g_btiles + (size_t)(t + 2) * TILE_BYTES),
                     TILE_BYTES, mb_bfull + 8 * buf);
        }
    }

    // ---- merge top-4 across the 4 lanes sharing each row
#pragma unroll
    for (int rr = 0; rr < 2; rr++) {
#pragma unroll
        for (int off = 1; off <= 2; off <<= 1) {
            float ov[4]; int oi[4];
#pragma unroll
            for (int q = 0; q < 4; q++) {
                ov[q] = __shfl_xor_sync(0xffffffffu, v4[rr][q], off);
                oi[q] = __shfl_xor_sync(0xffffffffu, ix4[rr][q], off);
            }
#pragma unroll
            for (int q = 0; q < 4; q++) ins4(ov[q], oi[q], v4[rr], ix4[rr]);
        }
        if ((l & 3) == 0) {
            const int id = s_map[w * 16 + (l >> 2) + rr * 8];
            g_ridx[id]  = ix4[rr][0];
            g_rmeta[id] = make_float2(v4[rr][0], v4[rr][1]);
            g_rcand[id] = make_int4(ix4[rr][0], ix4[rr][1], ix4[rr][2], ix4[rr][3]);
        }
    }
}

// ---------------------------------------------------------------- kernel 5: c0 = argmin ||c||^2
__global__ void prep_kernel() {
    __shared__ float sv[8];
    __shared__ int   si[8];
    int tid = threadIdx.x;
    float v = 3.4e38f; int ix = 0x7fffffff;
    for (int i = tid; i < KCODE; i += 256) {
        float c = g_cnorm[i];
        if (c < v || (c == v && i < ix)) { v = c; ix = i; }
    }
#pragma unroll
    for (int o = 16; o; o >>= 1) {
        float ov = __shfl_xor_sync(0xffffffffu, v, o);
        int   oi = __shfl_xor_sync(0xffffffffu, ix, o);
        if (ov < v || (ov == v && oi < ix)) { v = ov; ix = oi; }
    }
    if ((tid & 31) == 0) { sv[tid >> 5] = v; si[tid >> 5] = ix; }
    __syncthreads();
    if (tid == 0) {
#pragma unroll
        for (int q = 1; q < 8; q++)
            if (sv[q] < v || (sv[q] == v && si[q] < ix)) { v = sv[q]; ix = si[q]; }
        g_c0 = ix;
    }
}

// ---------------------------------------------------------------- kernel 6: exact fp32 rescore of near-ties
__global__ void rescore_kernel(const float* __restrict__ emb, const float* __restrict__ cb)
{
    int u = blockIdx.x * blockDim.x + threadIdx.x;
    if (u >= g_nuniq) return;
    const int id = g_uniq[u];
    float2 m = g_rmeta[id];
    if (m.y - m.x >= TAU) return;
    int4 cd = g_rcand[id];
    const int cods[4] = {cd.x, cd.y, cd.z, cd.w};
    const float* e = emb + (size_t)id * DIMN;

    float bestd = 3.4e38f; int besti = 0x7fffffff;
#pragma unroll
    for (int q = 0; q < 4; q++) {
        const int c = cods[q];
        const float* cp = cb + (size_t)c * DIMN;
        float a = 0.f, b = 0.f;
#pragma unroll 4
        for (int k = 0; k < DIMN; k += 2) {
            a = fmaf(e[k],     cp[k],     a);
            b = fmaf(e[k + 1], cp[k + 1], b);
        }
        float d = fmaf(-2.0f, a + b, g_cnorm[c]);
        if (d < bestd || (d == bestd && c < besti)) { bestd = d; besti = c; }
    }
    g_ridx[id] = besti;
}

// ---------------------------------------------------------------- kernel 7: means + encoder dense
// 4 batches per CTA (W re-read cut 4x), 512 threads: half-split over history.
__global__ void __launch_bounds__(512)
finish_kernel(const int* __restrict__ ids, const int* __restrict__ msk,
              const float* __restrict__ emb, const float* __restrict__ cb,
              const float* __restrict__ W,   const float* __restrict__ bias,
              float* __restrict__ out)
{
    __shared__ int   s_id[LL];
    __shared__ float s_m[LL];
    __shared__ int   s_vq[LL];
    __shared__ float s_x[FB][2 * DIMN];
    __shared__ float s_red[512];
    __shared__ int   s_cnt;

    const int tid = threadIdx.x;
    const int h   = tid >> 8;          // half: history slice
    const int d   = tid & 255;         // dim

    for (int fb = 0; fb < FB; fb++) {
        const int b = blockIdx.x * FB + fb;
        if (tid == 0) s_cnt = 0;
        __syncthreads();
        if (tid < LL) {
            int   id = ids[b * LL + tid];
            int   mv = msk[b * LL + tid];
            float m  = (mv >= 1) ? 1.f : 0.f;
            s_id[tid] = id;
            s_m[tid]  = m;
            s_vq[tid] = (mv >= 1) ? g_ridx[id] : g_c0;
            if (m > 0.f) atomicAdd(&s_cnt, 1);
        }
        __syncthreads();

        float hist = 0.f, vq = 0.f;
        const int l0 = h * 100, l1 = l0 + 100;
#pragma unroll 4
        for (int ll = l0; ll < l1; ll++) {
            hist = fmaf(emb[(size_t)s_id[ll] * DIMN + d], s_m[ll], hist);
            vq  += cb[(size_t)s_vq[ll] * DIMN + d];
        }
        s_red[tid] = vq;
        __syncthreads();
        if (h == 0) {
            const float cnt = (float)s_cnt;
            s_x[fb][d] = (s_red[d] + s_red[256 + d]) / cnt;
        }
        __syncthreads();
        s_red[tid] = hist;
        __syncthreads();
        if (h == 0) {
            const float cnt = (float)s_cnt;
            s_x[fb][DIMN + d] = (s_red[d] + s_red[256 + d]) / (cnt + 1e-9f);
        }
        __syncthreads();
    }

    // dense: thread (h,d) accumulates i in [h*256, h*256+256) for all FB batches
    float a[FB];
#pragma unroll
    for (int fb = 0; fb < FB; fb++) a[fb] = 0.f;
    const int i0 = h * DIMN;
#pragma unroll 4
    for (int i = 0; i < DIMN; i++) {
        const float wv = W[(size_t)(i0 + i) * DIMN + d];
#pragma unroll
        for (int fb = 0; fb < FB; fb++) a[fb] = fmaf(s_x[fb][i0 + i], wv, a[fb]);
    }
#pragma unroll
    for (int fb = 0; fb < FB; fb++) {
        s_red[tid] = a[fb];
        __syncthreads();
        if (h == 0) {
            const int b = blockIdx.x * FB + fb;
            out[(size_t)b * DIMN + d] = bias[d] + s_red[d] + s_red[256 + d];
        }
        __syncthreads();
    }
}

// ----------------------------------------------------------------
extern "C" void kernel_launch(void* const* d_in, const int* in_sizes, int n_in,
                              void* d_out, int out_size)
{
    const int*   ids  = (const int*)  d_in[0];
    const int*   msk  = (const int*)  d_in[1];
    const float* emb  = (const float*)d_in[2];
    const float* cb   = (const float*)d_in[3];
    const float* W    = (const float*)d_in[4];
    const float* bias = (const float*)d_in[5];
    float*       out  = (float*)d_out;

    cudaFuncSetAttribute(argmin_mma,
                         cudaFuncAttributeMaxDynamicSharedMemorySize, SMEM_TOTAL);

    cnorm_kernel<<<KCODE / 8, 256>>>(cb);                       // 1
    bsplit_kernel<<<(KCODE * (DIMN / 2)) / 256, 256>>>(cb);     // 2 (also resets dedup state)
    compact_kernel<<<(NROWS + 255) / 256, 256>>>(ids, msk);     // 3
    argmin_mma<<<MAXCTA, 256, SMEM_TOTAL>>>(emb);               // 4  <- ncu slot
    prep_kernel<<<1, 256>>>();                                  // 5
    rescore_kernel<<<(VOCAB + 255) / 256, 256>>>(emb, cb);      // 6
    finish_kernel<<<BB / FB, 512>>>(ids, msk, emb, cb, W, bias, out); // 7
}

// round 7
// speedup vs baseline: 1.0307x; 1.0307x over previous
#include <cuda_runtime.h>
#include <cuda_fp16.h>
#include <cstdint>
#include <cstddef>

// ---------------------------------------------------------------- constants
#define BB    512
#define LL    200
#define DIMN  256
#define KCODE 2048
#define NROWS (BB * LL)          // 102400
#define VOCAB 100000

#define MT    128                // unique ids per CTA
#define NTIL  64                 // codes per tile
#define NTT   32                 // total tiles
#define NTH   16                 // tiles per half-CTA
#define KSTEPS 17                // 16 data k-steps + 1 cnorm k-step
#define TILE_BYTES (KSTEPS * 4 * 512)   // 34816 (fragment-direct layout)
#define TAU   4e-3f
#define HCTA  (2 * ((VOCAB + MT - 1) / MT))   // 1564

// smem layout (argmin kernel)
#define SO_BAR  0                // mbarriers: bfull[2]@0,8  cons[2]@16,24
#define SO_MAP  64               // 128 ints
#define SO_B    1024             // 2 x 34816 B buffers (A staged here first)
#define SMEM_TOTAL (SO_B + 2 * TILE_BYTES)   // 70656

__device__ float  g_cnorm[KCODE];
__device__ int    g_mark[VOCAB];
__device__ int    g_uniq[VOCAB];
__device__ int    g_nuniq;
__device__ int    g_c0;
__device__ int    g_ridx[VOCAB];
__device__ float2 g_rmeta[VOCAB];
__device__ int4   g_rcand[VOCAB];
__device__ float4 g_rvalH[2 * VOCAB];    // per-half top-4 values
__device__ int4   g_rcandH[2 * VOCAB];   // per-half top-4 indices
__device__ __align__(16) unsigned char g_btiles[NTT * TILE_BYTES];  // ~1.1MB

// ---------------------------------------------------------------- PTX helpers
__device__ __forceinline__ uint32_t smem_u32(const void* p) {
    uint32_t a;
    asm("{ .reg .u64 t; cvta.to.shared.u64 t, %1; cvt.u32.u64 %0, t; }" : "=r"(a) : "l"(p));
    return a;
}
#define MBAR_INIT(a, n) asm volatile("mbarrier.init.shared.b64 [%0], %1;" :: "r"(a), "r"(n) : "memory")
#define MBAR_EXPECT_TX(a, b) asm volatile("mbarrier.arrive.expect_tx.shared.b64 _, [%0], %1;" :: "r"(a), "r"(b) : "memory")
#define MBAR_ARRIVE(a) asm volatile("mbarrier.arrive.shared.b64 _, [%0];" :: "r"(a) : "memory")
#define MBAR_WAIT(a, p) do {                                                   \
    asm volatile("{\n\t.reg .pred P1;\n\tWL%=:\n\t"                            \
        "mbarrier.try_wait.parity.acquire.cta.shared::cta.b64 P1, [%0], %1, 0x989680;\n\t" \
        "@P1 bra.uni WD%=;\n\tbra.uni WL%=;\n\tWD%=:\n\t}"                     \
        :: "r"(a), "r"(p) : "memory");                                         \
} while (0)
#define BULK_G2S(dst, src, bytes, mbar)                                        \
    asm volatile("cp.async.bulk.shared::cta.global.mbarrier::complete_tx::bytes [%0], [%1], %2, [%3];" \
                 :: "r"(dst), "l"(src), "r"(bytes), "r"(mbar) : "memory")

#define LDSM_X4(r, a)                                                          \
    asm volatile("ldmatrix.sync.aligned.m8n8.x4.shared.b16 {%0,%1,%2,%3}, [%4];" \
        : "=r"((r)[0]), "=r"((r)[1]), "=r"((r)[2]), "=r"((r)[3]) : "r"(a))
#define LDS128(r, a)                                                           \
    asm volatile("ld.shared.v4.b32 {%0,%1,%2,%3}, [%4];"                       \
        : "=r"((r)[0]), "=r"((r)[1]), "=r"((r)[2]), "=r"((r)[3]) : "r"(a))

__device__ __forceinline__ void mma_f16(float* d, const unsigned* a, const unsigned* b) {
    asm volatile("mma.sync.aligned.m16n8k16.row.col.f32.f16.f16.f32 "
        "{%0,%1,%2,%3}, {%4,%5,%6,%7}, {%8,%9}, {%0,%1,%2,%3};"
        : "+f"(d[0]), "+f"(d[1]), "+f"(d[2]), "+f"(d[3])
        : "r"(a[0]), "r"(a[1]), "r"(a[2]), "r"(a[3]), "r"(b[0]), "r"(b[1]));
}
// first k-step: D = A*B + 0 (kills acc-reset MOVs)
__device__ __forceinline__ void mma_f16_z(float* d, const unsigned* a, const unsigned* b) {
    asm volatile("mma.sync.aligned.m16n8k16.row.col.f32.f16.f16.f32 "
        "{%0,%1,%2,%3}, {%4,%5,%6,%7}, {%8,%9}, {%10,%10,%10,%10};"
        : "=f"(d[0]), "=f"(d[1]), "=f"(d[2]), "=f"(d[3])
        : "r"(a[0]), "r"(a[1]), "r"(a[2]), "r"(a[3]), "r"(b[0]), "r"(b[1]),
          "f"(0.0f));
}
__device__ __forceinline__ unsigned packh(float a, float b) {
    __half2 h = __floats2half2_rn(a, b);
    return *reinterpret_cast<unsigned*>(&h);
}
__device__ __forceinline__ void ins4(float d, int c, float v[4], int ix[4]) {
#pragma unroll
    for (int q = 0; q < 4; q++) {
        bool lt = (d < v[q]) || (d == v[q] && c < ix[q]);
        float tv = lt ? d : v[q];  int ti = lt ? c : ix[q];
        float nd = lt ? v[q] : d;  int nc = lt ? ix[q] : c;
        v[q] = tv; ix[q] = ti; d = nd; c = nc;
    }
}

// ---------------------------------------------------------------- kernel 1: ||c||^2
__global__ void cnorm_kernel(const float* __restrict__ cb) {
    int code = blockIdx.x * 8 + (threadIdx.x >> 5);
    int lane = threadIdx.x & 31;
    const float4* p = (const float4*)(cb + (size_t)code * DIMN);
    float s = 0.f;
#pragma unroll
    for (int i = 0; i < 2; i++) {
        float4 v = p[lane + 32 * i];
        s += v.x * v.x + v.y * v.y + v.z * v.z + v.w * v.w;
    }
#pragma unroll
    for (int o = 16; o; o >>= 1) s += __shfl_xor_sync(0xffffffffu, s, o);
    if (lane == 0) g_cnorm[code] = s;
}

// ---------------------------------------------------------------- kernel 2: fragment-direct fp16 tiles
// One u32 per thread. Tile layout: u32 at idx*512 + l*16 + r*4 where
// idx = ks*4 + jp holds B[n][k] mma fragments:
//   r0: (n_a, kk|kk+1)  r1: (n_a, kk+8|+9)  r2,r3: same with n_b = n_a + 8
//   n_a = jp*16 + (l>>2),  kk = ks*16 + (l&3)*2
// k-step 16 carries (cnorm_hi, cnorm_lo) at dims 256/257, zeros elsewhere.
__global__ void bsplit_kernel(const float* __restrict__ cb) {
    int gid = blockIdx.x * blockDim.x + threadIdx.x;   // 0 .. 278527
    if (gid < VOCAB) g_mark[gid] = 0;
    if (gid == 0) g_nuniq = 0;
    int tile = gid / (KSTEPS * 4 * 128);
    int rem  = gid % (KSTEPS * 4 * 128);
    int idx = rem >> 7;
    int li  = (rem >> 2) & 31;
    int r   = rem & 3;
    int ks  = idx >> 2, jp = idx & 3;
    int n  = tile * 64 + jp * 16 + ((r & 2) ? 8 : 0) + (li >> 2);
    int kk = ks * 16 + (li & 3) * 2 + ((r & 1) ? 8 : 0);
    unsigned val;
    if (ks < 16) {
        val = packh(cb[(size_t)n * DIMN + kk], cb[(size_t)n * DIMN + kk + 1]);
    } else if (((li & 3) == 0) && !(r & 1)) {   // dims 256,257 only
        float cn = g_cnorm[n];
        __half hi = __float2half_rn(cn);
        __half lo = __float2half_rn(cn - __half2float(hi));
        val = (unsigned)__half_as_ushort(hi) | ((unsigned)__half_as_ushort(lo) << 16);
    } else val = 0u;
    *(unsigned*)(g_btiles + (size_t)tile * TILE_BYTES
                 + (uint32_t)idx * 512u + (uint32_t)li * 16u + (uint32_t)r * 4u) = val;
}

// ---------------------------------------------------------------- kernel 3: collect unique valid ids
__global__ void compact_kernel(const int* __restrict__ ids, const int* __restrict__ msk) {
    int r = blockIdx.x * blockDim.x + threadIdx.x;
    if (r >= NROWS) return;
    if (msk[r] >= 1) {
        int id = ids[r];
        if (atomicExch(&g_mark[id], 1) == 0) {
            int pos = atomicAdd(&g_nuniq, 1);
            g_uniq[pos] = id;
        }
    }
}

// ---------------------------------------------------------------- kernel 4: fp16 HMMA argmin
// acc = sum(-2e . c) + cnorm  (distance directly). Code-split: blockIdx pairs,
// half = blockIdx&1 covers 1024 codes (16 tiles).
__global__ void __launch_bounds__(256, 2)
argmin_mma(const float* __restrict__ emb)
{
    extern __shared__ char smem[];
    const uint32_t sb  = smem_u32(smem);
    const int tid = threadIdx.x;
    const int l   = tid & 31;
    const int w   = tid >> 5;
    const int ublk = blockIdx.x >> 1;
    const int half = blockIdx.x & 1;
    const int r0   = ublk * MT;
    const int nuniq = g_nuniq;
    if (r0 >= nuniq) return;
    const int t0 = half * NTH;        // global tile range [t0, t0+16)
    int* s_map = (int*)(smem + SO_MAP);

    const uint32_t mb_bfull = sb + SO_BAR;
    const uint32_t mb_cons  = sb + SO_BAR + 16;

    if (tid == 0) {
        MBAR_INIT(mb_bfull + 0, 1); MBAR_INIT(mb_bfull + 8, 1);
        MBAR_INIT(mb_cons + 0, 8);  MBAR_INIT(mb_cons + 8, 8);
    }

    // ---- stage A = -2e (fp16) into B region temporarily (ldmatrix layout)
    {
        const int row  = tid >> 1, hf = tid & 1;
        int u = r0 + row; if (u >= nuniq) u = nuniq - 1;
        const int id = g_uniq[u];
        if (hf == 0) s_map[row] = id;
        const float4* ep = (const float4*)(emb + (size_t)id * DIMN + hf * 128);
        const uint32_t rowbase = (uint32_t)row * 512u;
        const uint32_t hb = (uint32_t)hf * 256u;
        const uint32_t xo = (uint32_t)(row & 7) << 4;
#pragma unroll
        for (int q = 0; q < 32; q++) {
            float4 v = ep[q];
            uint32_t off = rowbase + ((hb + (uint32_t)q * 8u) ^ xo);
            *(unsigned*)(smem + SO_B + off)     = packh(-2.f * v.x, -2.f * v.y);
            *(unsigned*)(smem + SO_B + off + 4) = packh(-2.f * v.z, -2.f * v.w);
        }
    }
    __syncthreads();

    const uint32_t xorv   = (uint32_t)(l & 7) << 4;
    const uint32_t arow   = (uint32_t)(w * 16 + (l & 7) + ((l >> 3) & 1) * 8);
    const uint32_t koff_a = (uint32_t)((l >> 4) & 1) * 16u;

    // ---- A fragments (k-steps 0..15) -> persistent registers
    unsigned ah[16][4];
    {
        const uint32_t a_b = sb + SO_B + arow * 512u;
#pragma unroll
        for (int s = 0; s < 16; s++)
            LDSM_X4(ah[s], a_b + (((uint32_t)(s * 32) + koff_a) ^ xorv));
    }
    // k-step 16 fragment: A[*][256]=A[*][257]=1, rest 0 -> compile-time constant
    unsigned ah16[4];
    ah16[0] = ah16[1] = ((l & 3) == 0) ? 0x3C003C00u : 0u;
    ah16[2] = ah16[3] = 0u;
    __syncthreads();   // staging region free -> B double buffer

    if (tid == 0) {
        MBAR_EXPECT_TX(mb_bfull + 0, TILE_BYTES);
        BULK_G2S(sb + SO_B, (const void*)(g_btiles + (size_t)t0 * TILE_BYTES),
                 TILE_BYTES, mb_bfull + 0);
        MBAR_EXPECT_TX(mb_bfull + 8, TILE_BYTES);
        BULK_G2S(sb + SO_B + TILE_BYTES,
                 (const void*)(g_btiles + (size_t)(t0 + 1) * TILE_BYTES),
                 TILE_BYTES, mb_bfull + 8);
    }

    float acc[8][4];
    float v4[2][4]; int ix4[2][4];
#pragma unroll
    for (int rr = 0; rr < 2; rr++)
#pragma unroll
        for (int q = 0; q < 4; q++) { v4[rr][q] = 3.4e38f; ix4[rr][q] = 0x7fffffff; }

    int bpar[2] = {0, 0}, cpar[2] = {0, 0};

    for (int t = 0; t < NTH; t++) {
        const int buf = t & 1;
        const uint32_t Rb = sb + SO_B + (uint32_t)buf * TILE_BYTES + (uint32_t)l * 16u;
        MBAR_WAIT(mb_bfull + 8 * buf, (uint32_t)bpar[buf]); bpar[buf] ^= 1;

        unsigned b4[2][4];
        LDS128(b4[0], Rb);
#pragma unroll
        for (int idx = 0; idx < 68; idx++) {
            const int cur = idx & 1;
            if (idx < 67) LDS128(b4[cur ^ 1], Rb + (uint32_t)(idx + 1) * 512u);
            const int ks = idx >> 2, jp = idx & 3;
            const unsigned* af = (ks == 16) ? ah16 : ah[ks];
            if (idx < 4) {
                mma_f16_z(acc[2 * jp],     af, b4[cur]);
                mma_f16_z(acc[2 * jp + 1], af, b4[cur] + 2);
            } else {
                mma_f16(acc[2 * jp],     af, b4[cur]);
                mma_f16(acc[2 * jp + 1], af, b4[cur] + 2);
            }
        }
        if (l == 0) MBAR_ARRIVE(mb_cons + 8 * buf);

        // epilogue: acc IS the distance; compare-only with rare insert
        const int cbase = (t0 + t) * NTIL;
#pragma unroll
        for (int j = 0; j < 8; j++) {
#pragma unroll
            for (int e = 0; e < 4; e++) {
                const int rr   = e >> 1;
                const int code = cbase + (j >> 1) * 16 + (j & 1) * 8 + 2 * (l & 3) + (e & 1);
                const float dist = acc[j][e];
                if (dist < v4[rr][3]) ins4(dist, code, v4[rr], ix4[rr]);
            }
        }

        if (tid == 0 && t + 2 < NTH) {
            MBAR_WAIT(mb_cons + 8 * buf, (uint32_t)cpar[buf]); cpar[buf] ^= 1;
            MBAR_EXPECT_TX(mb_bfull + 8 * buf, TILE_BYTES);
            BULK_G2S(sb + SO_B + (uint32_t)buf * TILE_BYTES,
                     (const void*)(g_btiles + (size_t)(t0 + t + 2) * TILE_BYTES),
                     TILE_BYTES, mb_bfull + 8 * buf);
        }
    }

    // ---- merge top-4 across the 4 lanes sharing each row
#pragma unroll
    for (int rr = 0; rr < 2; rr++) {
#pragma unroll
        for (int off = 1; off <= 2; off <<= 1) {
            float ov[4]; int oi[4];
#pragma unroll
            for (int q = 0; q < 4; q++) {
                ov[q] = __shfl_xor_sync(0xffffffffu, v4[rr][q], off);
                oi[q] = __shfl_xor_sync(0xffffffffu, ix4[rr][q], off);
            }
#pragma unroll
            for (int q = 0; q < 4; q++) ins4(ov[q], oi[q], v4[rr], ix4[rr]);
        }
        if ((l & 3) == 0) {
            const int id = s_map[w * 16 + (l >> 2) + rr * 8];
            g_rvalH[half * VOCAB + id]  = make_float4(v4[rr][0], v4[rr][1], v4[rr][2], v4[rr][3]);
            g_rcandH[half * VOCAB + id] = make_int4(ix4[rr][0], ix4[rr][1], ix4[rr][2], ix4[rr][3]);
        }
    }
}

// ---------------------------------------------------------------- kernel 5: c0 = argmin ||c||^2
__global__ void prep_kernel() {
    __shared__ float sv[8];
    __shared__ int   si[8];
    int tid = threadIdx.x;
    float v = 3.4e38f; int ix = 0x7fffffff;
    for (int i = tid; i < KCODE; i += 256) {
        float c = g_cnorm[i];
        if (c < v || (c == v && i < ix)) { v = c; ix = i; }
    }
#pragma unroll
    for (int o = 16; o; o >>= 1) {
        float ov = __shfl_xor_sync(0xffffffffu, v, o);
        int   oi = __shfl_xor_sync(0xffffffffu, ix, o);
        if (ov < v || (ov == v && oi < ix)) { v = ov; ix = oi; }
    }
    if ((tid & 31) == 0) { sv[tid >> 5] = v; si[tid >> 5] = ix; }
    __syncthreads();
    if (tid == 0) {
#pragma unroll
        for (int q = 1; q < 8; q++)
            if (sv[q] < v || (sv[q] == v && si[q] < ix)) { v = sv[q]; ix = si[q]; }
        g_c0 = ix;
    }
}

// ---------------------------------------------------------------- kernel 6: merge the two code-halves
__global__ void merge_kernel() {
    int u = blockIdx.x * blockDim.x + threadIdx.x;
    if (u >= g_nuniq) return;
    const int id = g_uniq[u];
    float4 va = g_rvalH[id];           int4 ca = g_rcandH[id];
    float4 vb = g_rvalH[VOCAB + id];   int4 cbv = g_rcandH[VOCAB + id];
    float v4[4] = {va.x, va.y, va.z, va.w};
    int   ix4[4] = {ca.x, ca.y, ca.z, ca.w};
    ins4(vb.x, cbv.x, v4, ix4);
    ins4(vb.y, cbv.y, v4, ix4);
    ins4(vb.z, cbv.z, v4, ix4);
    ins4(vb.w, cbv.w, v4, ix4);
    g_ridx[id]  = ix4[0];
    g_rmeta[id] = make_float2(v4[0], v4[1]);
    g_rcand[id] = make_int4(ix4[0], ix4[1], ix4[2], ix4[3]);
}

// ---------------------------------------------------------------- kernel 7: exact fp32 rescore of near-ties
__global__ void rescore_kernel(const float* __restrict__ emb, const float* __restrict__ cb)
{
    int u = blockIdx.x * blockDim.x + threadIdx.x;
    if (u >= g_nuniq) return;
    const int id = g_uniq[u];
    float2 m = g_rmeta[id];
    if (m.y - m.x >= TAU) return;
    int4 cd = g_rcand[id];
    const int cods[4] = {cd.x, cd.y, cd.z, cd.w};
    const float* e = emb + (size_t)id * DIMN;

    float bestd = 3.4e38f; int besti = 0x7fffffff;
#pragma unroll
    for (int q = 0; q < 4; q++) {
        const int c = cods[q];
        const float* cp = cb + (size_t)c * DIMN;
        float a = 0.f, b = 0.f;
#pragma unroll 4
        for (int k = 0; k < DIMN; k += 2) {
            a = fmaf(e[k],     cp[k],     a);
            b = fmaf(e[k + 1], cp[k + 1], b);
        }
        float d = fmaf(-2.0f, a + b, g_cnorm[c]);
        if (d < bestd || (d == bestd && c < besti)) { bestd = d; besti = c; }
    }
    g_ridx[id] = besti;
}

// ---------------------------------------------------------------- kernel 8: means + encoder dense
__global__ void __launch_bounds__(256)
finish_kernel(const int* __restrict__ ids, const int* __restrict__ msk,
              const float* __restrict__ emb, const float* __restrict__ cb,
              const float* __restrict__ W,   const float* __restrict__ bias,
              float* __restrict__ out)
{
    __shared__ int   s_id[LL];
    __shared__ float s_m[LL];
    __shared__ int   s_vq[LL];
    __shared__ float s_x[2 * DIMN];
    __shared__ int   s_cnt;

    const int b = blockIdx.x, tid = threadIdx.x;
    if (tid == 0) s_cnt = 0;
    __syncthreads();
    if (tid < LL) {
        int   id = ids[b * LL + tid];
        int   mv = msk[b * LL + tid];
        float m  = (mv >= 1) ? 1.f : 0.f;
        s_id[tid] = id;
        s_m[tid]  = m;
        s_vq[tid] = (mv >= 1) ? g_ridx[id] : g_c0;
        if (m > 0.f) atomicAdd(&s_cnt, 1);
    }
    __syncthreads();

    const float cnt = (float)s_cnt;
    const int   d   = tid;
    float hist = 0.f, vq = 0.f;
#pragma unroll 4
    for (int ll = 0; ll < LL; ll++) {
        hist = fmaf(emb[(size_t)s_id[ll] * DIMN + d], s_m[ll], hist);
        vq  += cb[(size_t)s_vq[ll] * DIMN + d];
    }
    s_x[d]        = vq / cnt;
    s_x[DIMN + d] = hist / (cnt + 1e-9f);
    __syncthreads();

    float a0 = bias[d], a1 = 0.f;
#pragma unroll 8
    for (int i = 0; i < DIMN; i++) {
        a0 = fmaf(s_x[i],        W[(size_t)i * DIMN + d],          a0);
        a1 = fmaf(s_x[DIMN + i], W[(size_t)(DIMN + i) * DIMN + d], a1);
    }
    out[(size_t)b * DIMN + d] = a0 + a1;
}

// ----------------------------------------------------------------
extern "C" void kernel_launch(void* const* d_in, const int* in_sizes, int n_in,
                              void* d_out, int out_size)
{
    const int*   ids  = (const int*)  d_in[0];
    const int*   msk  = (const int*)  d_in[1];
    const float* emb  = (const float*)d_in[2];
    const float* cb   = (const float*)d_in[3];
    const float* W    = (const float*)d_in[4];
    const float* bias = (const float*)d_in[5];
    float*       out  = (float*)d_out;

    cudaFuncSetAttribute(argmin_mma,
                         cudaFuncAttributeMaxDynamicSharedMemorySize, SMEM_TOTAL);

    cnorm_kernel<<<KCODE / 8, 256>>>(cb);                          // 1
    bsplit_kernel<<<(NTT * KSTEPS * 4 * 128) / 256, 256>>>(cb);    // 2
    compact_kernel<<<(NROWS + 255) / 256, 256>>>(ids, msk);        // 3
    argmin_mma<<<HCTA, 256, SMEM_TOTAL>>>(emb);                    // 4
    prep_kernel<<<1, 256>>>();                                     // 5
    merge_kernel<<<(VOCAB + 255) / 256, 256>>>();                  // 6
    rescore_kernel<<<(VOCAB + 255) / 256, 256>>>(emb, cb);         // 7
    finish_kernel<<<BB, 256>>>(ids, msk, emb, cb, W, bias, out);   // 8
}

// round 8
// speedup vs baseline: 1.0759x; 1.0438x over previous
#include <cuda_runtime.h>
#include <cuda_fp16.h>
#include <cstdint>
#include <cstddef>

// ---------------------------------------------------------------- constants
#define BB    512
#define LL    200
#define DIMN  256
#define KCODE 2048
#define NROWS (BB * LL)          // 102400
#define VOCAB 100000

#define MT    128                // unique ids per CTA
#define NTIL  64                 // codes per tile
#define NTT   32                 // total tiles
#define NTH   16                 // tiles per half-CTA
#define KSTEPS 17                // 16 data k-steps + 1 cnorm k-step
#define TILE_BYTES (KSTEPS * 4 * 512)   // 34816 (fragment-direct layout)
#define TAU   4e-3f
#define HCTA  (2 * ((VOCAB + MT - 1) / MT))   // 1564

// smem layout (argmin kernel)
#define SO_BAR  0                // mbarriers: bfull[2]@0,8  cons[2]@16,24
#define SO_MAP  64               // 128 ints
#define SO_B    1024             // 2 x 34816 B buffers (A staged here first)
#define SMEM_TOTAL (SO_B + 2 * TILE_BYTES)   // 70656

__device__ float  g_cnorm[KCODE];
__device__ int    g_mark[VOCAB];
__device__ int    g_uniq[VOCAB];
__device__ int    g_nuniq;
__device__ unsigned long long g_c0enc = 0xFFFFFFFFFFFFFFFFull;  // (distbits<<32)|idx
__device__ int    g_ridx[VOCAB];
__device__ float4 g_rvalH[2 * VOCAB];    // per-half top-4 values
__device__ int4   g_rcandH[2 * VOCAB];   // per-half top-4 indices
__device__ __align__(16) unsigned char g_btiles[NTT * TILE_BYTES];  // ~1.1MB

// ---------------------------------------------------------------- PTX helpers
__device__ __forceinline__ uint32_t smem_u32(const void* p) {
    uint32_t a;
    asm("{ .reg .u64 t; cvta.to.shared.u64 t, %1; cvt.u32.u64 %0, t; }" : "=r"(a) : "l"(p));
    return a;
}
#define MBAR_INIT(a, n) asm volatile("mbarrier.init.shared.b64 [%0], %1;" :: "r"(a), "r"(n) : "memory")
#define MBAR_EXPECT_TX(a, b) asm volatile("mbarrier.arrive.expect_tx.shared.b64 _, [%0], %1;" :: "r"(a), "r"(b) : "memory")
#define MBAR_ARRIVE(a) asm volatile("mbarrier.arrive.shared.b64 _, [%0];" :: "r"(a) : "memory")
#define MBAR_WAIT(a, p) do {                                                   \
    asm volatile("{\n\t.reg .pred P1;\n\tWL%=:\n\t"                            \
        "mbarrier.try_wait.parity.acquire.cta.shared::cta.b64 P1, [%0], %1, 0x989680;\n\t" \
        "@P1 bra.uni WD%=;\n\tbra.uni WL%=;\n\tWD%=:\n\t}"                     \
        :: "r"(a), "r"(p) : "memory");                                         \
} while (0)
#define BULK_G2S(dst, src, bytes, mbar)                                        \
    asm volatile("cp.async.bulk.shared::cta.global.mbarrier::complete_tx::bytes [%0], [%1], %2, [%3];" \
                 :: "r"(dst), "l"(src), "r"(bytes), "r"(mbar) : "memory")

#define LDSM_X4(r, a)                                                          \
    asm volatile("ldmatrix.sync.aligned.m8n8.x4.shared.b16 {%0,%1,%2,%3}, [%4];" \
        : "=r"((r)[0]), "=r"((r)[1]), "=r"((r)[2]), "=r"((r)[3]) : "r"(a))
#define LDS128(r, a)                                                           \
    asm volatile("ld.shared.v4.b32 {%0,%1,%2,%3}, [%4];"                       \
        : "=r"((r)[0]), "=r"((r)[1]), "=r"((r)[2]), "=r"((r)[3]) : "r"(a))

__device__ __forceinline__ void mma_f16(float* d, const unsigned* a, const unsigned* b) {
    asm volatile("mma.sync.aligned.m16n8k16.row.col.f32.f16.f16.f32 "
        "{%0,%1,%2,%3}, {%4,%5,%6,%7}, {%8,%9}, {%0,%1,%2,%3};"
        : "+f"(d[0]), "+f"(d[1]), "+f"(d[2]), "+f"(d[3])
        : "r"(a[0]), "r"(a[1]), "r"(a[2]), "r"(a[3]), "r"(b[0]), "r"(b[1]));
}
__device__ __forceinline__ void mma_f16_z(float* d, const unsigned* a, const unsigned* b) {
    asm volatile("mma.sync.aligned.m16n8k16.row.col.f32.f16.f16.f32 "
        "{%0,%1,%2,%3}, {%4,%5,%6,%7}, {%8,%9}, {%10,%10,%10,%10};"
        : "=f"(d[0]), "=f"(d[1]), "=f"(d[2]), "=f"(d[3])
        : "r"(a[0]), "r"(a[1]), "r"(a[2]), "r"(a[3]), "r"(b[0]), "r"(b[1]),
          "f"(0.0f));
}
__device__ __forceinline__ unsigned packh(float a, float b) {
    __half2 h = __floats2half2_rn(a, b);
    return *reinterpret_cast<unsigned*>(&h);
}
__device__ __forceinline__ void ins4(float d, int c, float v[4], int ix[4]) {
#pragma unroll
    for (int q = 0; q < 4; q++) {
        bool lt = (d < v[q]) || (d == v[q] && c < ix[q]);
        float tv = lt ? d : v[q];  int ti = lt ? c : ix[q];
        float nd = lt ? v[q] : d;  int nc = lt ? ix[q] : c;
        v[q] = tv; ix[q] = ti; d = nd; c = nc;
    }
}

// ---------------------------------------------------------------- kernel 1: ||c||^2 + global argmin (c0)
__global__ void cnorm_kernel(const float* __restrict__ cb) {
    int code = blockIdx.x * 8 + (threadIdx.x >> 5);
    int lane = threadIdx.x & 31;
    const float4* p = (const float4*)(cb + (size_t)code * DIMN);
    float s = 0.f;
#pragma unroll
    for (int i = 0; i < 2; i++) {
        float4 v = p[lane + 32 * i];
        s += v.x * v.x + v.y * v.y + v.z * v.z + v.w * v.w;
    }
#pragma unroll
    for (int o = 16; o; o >>= 1) s += __shfl_xor_sync(0xffffffffu, s, o);
    if (lane == 0) {
        g_cnorm[code] = s;
        // s >= 0 -> float bits monotone; min over (dist, idx) lexicographic.
        unsigned long long enc = ((unsigned long long)__float_as_uint(s) << 32)
                               | (unsigned)code;
        atomicMin(&g_c0enc, enc);   // idempotent across graph replays
    }
}

// ---------------------------------------------------------------- kernel 2: fragment-direct fp16 tiles
__global__ void bsplit_kernel(const float* __restrict__ cb) {
    int gid = blockIdx.x * blockDim.x + threadIdx.x;   // 0 .. 278527
    if (gid < VOCAB) g_mark[gid] = 0;
    if (gid == 0) g_nuniq = 0;
    int tile = gid / (KSTEPS * 4 * 128);
    int rem  = gid % (KSTEPS * 4 * 128);
    int idx = rem >> 7;
    int li  = (rem >> 2) & 31;
    int r   = rem & 3;
    int ks  = idx >> 2, jp = idx & 3;
    int n  = tile * 64 + jp * 16 + ((r & 2) ? 8 : 0) + (li >> 2);
    int kk = ks * 16 + (li & 3) * 2 + ((r & 1) ? 8 : 0);
    unsigned val;
    if (ks < 16) {
        val = packh(cb[(size_t)n * DIMN + kk], cb[(size_t)n * DIMN + kk + 1]);
    } else if (((li & 3) == 0) && !(r & 1)) {   // dims 256,257 only
        float cn = g_cnorm[n];
        __half hi = __float2half_rn(cn);
        __half lo = __float2half_rn(cn - __half2float(hi));
        val = (unsigned)__half_as_ushort(hi) | ((unsigned)__half_as_ushort(lo) << 16);
    } else val = 0u;
    *(unsigned*)(g_btiles + (size_t)tile * TILE_BYTES
                 + (uint32_t)idx * 512u + (uint32_t)li * 16u + (uint32_t)r * 4u) = val;
}

// ---------------------------------------------------------------- kernel 3: collect unique valid ids
__global__ void compact_kernel(const int* __restrict__ ids, const int* __restrict__ msk) {
    int r = blockIdx.x * blockDim.x + threadIdx.x;
    if (r >= NROWS) return;
    if (msk[r] >= 1) {
        int id = ids[r];
        if (atomicExch(&g_mark[id], 1) == 0) {
            int pos = atomicAdd(&g_nuniq, 1);
            g_uniq[pos] = id;
        }
    }
}

// ---------------------------------------------------------------- kernel 4: fp16 HMMA argmin
// Two jp-passes per tile; 4-deep B prefetch ring; acc IS the distance.
__global__ void __launch_bounds__(256, 2)
argmin_mma(const float* __restrict__ emb)
{
    extern __shared__ char smem[];
    const uint32_t sb  = smem_u32(smem);
    const int tid = threadIdx.x;
    const int l   = tid & 31;
    const int w   = tid >> 5;
    const int ublk = blockIdx.x >> 1;
    const int half = blockIdx.x & 1;
    const int r0   = ublk * MT;
    const int nuniq = g_nuniq;
    if (r0 >= nuniq) return;
    const int t0 = half * NTH;
    int* s_map = (int*)(smem + SO_MAP);

    const uint32_t mb_bfull = sb + SO_BAR;
    const uint32_t mb_cons  = sb + SO_BAR + 16;

    if (tid == 0) {
        MBAR_INIT(mb_bfull + 0, 1); MBAR_INIT(mb_bfull + 8, 1);
        MBAR_INIT(mb_cons + 0, 8);  MBAR_INIT(mb_cons + 8, 8);
    }

    // ---- stage A = -2e (fp16) into B region temporarily (ldmatrix layout)
    {
        const int row  = tid >> 1, hf = tid & 1;
        int u = r0 + row; if (u >= nuniq) u = nuniq - 1;
        const int id = g_uniq[u];
        if (hf == 0) s_map[row] = id;
        const float4* ep = (const float4*)(emb + (size_t)id * DIMN + hf * 128);
        const uint32_t rowbase = (uint32_t)row * 512u;
        const uint32_t hb = (uint32_t)hf * 256u;
        const uint32_t xo = (uint32_t)(row & 7) << 4;
#pragma unroll
        for (int q = 0; q < 32; q++) {
            float4 v = ep[q];
            uint32_t off = rowbase + ((hb + (uint32_t)q * 8u) ^ xo);
            *(unsigned*)(smem + SO_B + off)     = packh(-2.f * v.x, -2.f * v.y);
            *(unsigned*)(smem + SO_B + off + 4) = packh(-2.f * v.z, -2.f * v.w);
        }
    }
    __syncthreads();

    const uint32_t xorv   = (uint32_t)(l & 7) << 4;
    const uint32_t arow   = (uint32_t)(w * 16 + (l & 7) + ((l >> 3) & 1) * 8);
    const uint32_t koff_a = (uint32_t)((l >> 4) & 1) * 16u;

    // ---- A fragments (k-steps 0..15) -> persistent registers (64 regs)
    unsigned ah[16][4];
    {
        const uint32_t a_b = sb + SO_B + arow * 512u;
#pragma unroll
        for (int s = 0; s < 16; s++)
            LDSM_X4(ah[s], a_b + (((uint32_t)(s * 32) + koff_a) ^ xorv));
    }
    // cnorm k-step A fragment (compile-time-ish constant)
    unsigned ah16[4];
    ah16[0] = ah16[1] = ((l & 3) == 0) ? 0x3C003C00u : 0u;
    ah16[2] = ah16[3] = 0u;
    __syncthreads();   // staging region free -> B double buffer

    if (tid == 0) {
        MBAR_EXPECT_TX(mb_bfull + 0, TILE_BYTES);
        BULK_G2S(sb + SO_B, (const void*)(g_btiles + (size_t)t0 * TILE_BYTES),
                 TILE_BYTES, mb_bfull + 0);
        MBAR_EXPECT_TX(mb_bfull + 8, TILE_BYTES);
        BULK_G2S(sb + SO_B + TILE_BYTES,
                 (const void*)(g_btiles + (size_t)(t0 + 1) * TILE_BYTES),
                 TILE_BYTES, mb_bfull + 8);
    }

    float v4[2][4]; int ix4[2][4];
#pragma unroll
    for (int rr = 0; rr < 2; rr++)
#pragma unroll
        for (int q = 0; q < 4; q++) { v4[rr][q] = 3.4e38f; ix4[rr][q] = 0x7fffffff; }

    int bpar[2] = {0, 0}, cpar[2] = {0, 0};
    const int cb_l = 2 * (l & 3);

    for (int t = 0; t < NTH; t++) {
        const int buf = t & 1;
        const uint32_t Rb = sb + SO_B + (uint32_t)buf * TILE_BYTES + (uint32_t)l * 16u;
        MBAR_WAIT(mb_bfull + 8 * buf, (uint32_t)bpar[buf]); bpar[buf] ^= 1;

#pragma unroll
        for (int p = 0; p < 2; p++) {
            const uint32_t Rbp = Rb + (uint32_t)p * 1024u;
            float acc[4][4];
            unsigned b4[4][4];
            // prime 4-deep ring: ii -> offset (ii>>1)*2048 + (ii&1)*512
            LDS128(b4[0], Rbp);
            LDS128(b4[1], Rbp + 512u);
            LDS128(b4[2], Rbp + 2048u);
            LDS128(b4[3], Rbp + 2560u);
#pragma unroll
            for (int ii = 0; ii < 34; ii++) {
                const int cur = ii & 3;
                const int ks  = ii >> 1;
                const int jl  = ii & 1;
                const unsigned* af = (ks == 16) ? ah16 : ah[ks];
                if (ii < 2) {
                    mma_f16_z(acc[2 * jl],     af, b4[cur]);
                    mma_f16_z(acc[2 * jl + 1], af, b4[cur] + 2);
                } else {
                    mma_f16(acc[2 * jl],     af, b4[cur]);
                    mma_f16(acc[2 * jl + 1], af, b4[cur] + 2);
                }
                if (ii + 4 < 34) {
                    const uint32_t noff = (uint32_t)(((ii + 4) >> 1) * 2048 + ((ii + 4) & 1) * 512);
                    LDS128(b4[cur], Rbp + noff);
                }
            }
            // epilogue for this pass's 32 codes
            const int cbase = (t0 + t) * NTIL + p * 32 + cb_l;
#pragma unroll
            for (int j = 0; j < 4; j++) {
#pragma unroll
                for (int e = 0; e < 4; e++) {
                    const int rr   = e >> 1;
                    const int code = cbase + (j >> 1) * 16 + (j & 1) * 8 + (e & 1);
                    const float dist = acc[j][e];
                    if (dist < v4[rr][3]) ins4(dist, code, v4[rr], ix4[rr]);
                }
            }
        }
        if (l == 0) MBAR_ARRIVE(mb_cons + 8 * buf);

        if (tid == 0 && t + 2 < NTH) {
            MBAR_WAIT(mb_cons + 8 * buf, (uint32_t)cpar[buf]); cpar[buf] ^= 1;
            MBAR_EXPECT_TX(mb_bfull + 8 * buf, TILE_BYTES);
            BULK_G2S(sb + SO_B + (uint32_t)buf * TILE_BYTES,
                     (const void*)(g_btiles + (size_t)(t0 + t + 2) * TILE_BYTES),
                     TILE_BYTES, mb_bfull + 8 * buf);
        }
    }

    // ---- merge top-4 across the 4 lanes sharing each row
#pragma unroll
    for (int rr = 0; rr < 2; rr++) {
#pragma unroll
        for (int off = 1; off <= 2; off <<= 1) {
            float ov[4]; int oi[4];
#pragma unroll
            for (int q = 0; q < 4; q++) {
                ov[q] = __shfl_xor_sync(0xffffffffu, v4[rr][q], off);
                oi[q] = __shfl_xor_sync(0xffffffffu, ix4[rr][q], off);
            }
#pragma unroll
            for (int q = 0; q < 4; q++) ins4(ov[q], oi[q], v4[rr], ix4[rr]);
        }
        if ((l & 3) == 0) {
            const int id = s_map[w * 16 + (l >> 2) + rr * 8];
            g_rvalH[half * VOCAB + id]  = make_float4(v4[rr][0], v4[rr][1], v4[rr][2], v4[rr][3]);
            g_rcandH[half * VOCAB + id] = make_int4(ix4[rr][0], ix4[rr][1], ix4[rr][2], ix4[rr][3]);
        }
    }
}

// ---------------------------------------------------------------- kernel 5: merge halves + exact rescore
__global__ void rescore_kernel(const float* __restrict__ emb, const float* __restrict__ cb,
                               const float* __restrict__ cn_unused)
{
    int u = blockIdx.x * blockDim.x + threadIdx.x;
    if (u >= g_nuniq) return;
    const int id = g_uniq[u];
    float4 va = g_rvalH[id];           int4 ca  = g_rcandH[id];
    float4 vb = g_rvalH[VOCAB + id];   int4 cbv = g_rcandH[VOCAB + id];
    float v4[4]  = {va.x, va.y, va.z, va.w};
    int   ix4[4] = {ca.x, ca.y, ca.z, ca.w};
    ins4(vb.x, cbv.x, v4, ix4);
    ins4(vb.y, cbv.y, v4, ix4);
    ins4(vb.z, cbv.z, v4, ix4);
    ins4(vb.w, cbv.w, v4, ix4);
    if (v4[1] - v4[0] >= TAU) { g_ridx[id] = ix4[0]; return; }

    const float* e = emb + (size_t)id * DIMN;
    float bestd = 3.4e38f; int besti = 0x7fffffff;
#pragma unroll
    for (int q = 0; q < 4; q++) {
        const int c = ix4[q];
        const float* cp = cb + (size_t)c * DIMN;
        float a = 0.f, b = 0.f;
#pragma unroll 4
        for (int k = 0; k < DIMN; k += 2) {
            a = fmaf(e[k],     cp[k],     a);
            b = fmaf(e[k + 1], cp[k + 1], b);
        }
        float d = fmaf(-2.0f, a + b, g_cnorm[c]);
        if (d < bestd || (d == bestd && c < besti)) { bestd = d; besti = c; }
    }
    g_ridx[id] = besti;
}

// ---------------------------------------------------------------- kernel 6: means + encoder dense
__global__ void __launch_bounds__(256)
finish_kernel(const int* __restrict__ ids, const int* __restrict__ msk,
              const float* __restrict__ emb, const float* __restrict__ cb,
              const float* __restrict__ W,   const float* __restrict__ bias,
              float* __restrict__ out)
{
    __shared__ int   s_id[LL];
    __shared__ float s_m[LL];
    __shared__ int   s_vq[LL];
    __shared__ float s_x[2 * DIMN];
    __shared__ int   s_cnt;

    const int b = blockIdx.x, tid = threadIdx.x;
    if (tid == 0) s_cnt = 0;
    __syncthreads();
    const int c0 = (int)(unsigned)(g_c0enc & 0xFFFFFFFFull);
    if (tid < LL) {
        int   id = ids[b * LL + tid];
        int   mv = msk[b * LL + tid];
        float m  = (mv >= 1) ? 1.f : 0.f;
        s_id[tid] = id;
        s_m[tid]  = m;
        s_vq[tid] = (mv >= 1) ? g_ridx[id] : c0;
        if (m > 0.f) atomicAdd(&s_cnt, 1);
    }
    __syncthreads();

    const float cnt = (float)s_cnt;
    const int   d   = tid;
    float hist = 0.f, vq = 0.f;
#pragma unroll 4
    for (int ll = 0; ll < LL; ll++) {
        hist = fmaf(emb[(size_t)s_id[ll] * DIMN + d], s_m[ll], hist);
        vq  += cb[(size_t)s_vq[ll] * DIMN + d];
    }
    s_x[d]        = vq / cnt;
    s_x[DIMN + d] = hist / (cnt + 1e-9f);
    __syncthreads();

    float a0 = bias[d], a1 = 0.f;
#pragma unroll 8
    for (int i = 0; i < DIMN; i++) {
        a0 = fmaf(s_x[i],        W[(size_t)i * DIMN + d],          a0);
        a1 = fmaf(s_x[DIMN + i], W[(size_t)(DIMN + i) * DIMN + d], a1);
    }
    out[(size_t)b * DIMN + d] = a0 + a1;
}

// ----------------------------------------------------------------
extern "C" void kernel_launch(void* const* d_in, const int* in_sizes, int n_in,
                              void* d_out, int out_size)
{
    const int*   ids  = (const int*)  d_in[0];
    const int*   msk  = (const int*)  d_in[1];
    const float* emb  = (const float*)d_in[2];
    const float* cb   = (const float*)d_in[3];
    const float* W    = (const float*)d_in[4];
    const float* bias = (const float*)d_in[5];
    float*       out  = (float*)d_out;

    cudaFuncSetAttribute(argmin_mma,
                         cudaFuncAttributeMaxDynamicSharedMemorySize, SMEM_TOTAL);

    cnorm_kernel<<<KCODE / 8, 256>>>(cb);                          // 1 (+ c0 atomicMin)
    bsplit_kernel<<<(NTT * KSTEPS * 4 * 128) / 256, 256>>>(cb);    // 2
    compact_kernel<<<(NROWS + 255) / 256, 256>>>(ids, msk);        // 3
    argmin_mma<<<HCTA, 256, SMEM_TOTAL>>>(emb);                    // 4
    rescore_kernel<<<(VOCAB + 255) / 256, 256>>>(emb, cb, nullptr);// 5 (merge+rescore)
    finish_kernel<<<BB, 256>>>(ids, msk, emb, cb, W, bias, out);   // 6
}

// round 10
// speedup vs baseline: 1.2895x; 1.1985x over previous
#include <cuda_runtime.h>
#include <cuda_fp16.h>
#include <cstdint>
#include <cstddef>

// ---------------------------------------------------------------- constants
#define BB    512
#define LL    200
#define DIMN  256
#define KCODE 2048
#define NROWS (BB * LL)          // 102400
#define VOCAB 100000

#define MT    128                // unique ids per CTA
#define NTIL  64                 // codes per tile
#define NTT   32                 // total tiles
#define NTH   16                 // tiles per half-CTA
#define KSTEPS 17                // 16 data k-steps + 1 cnorm k-step
#define TILE_BYTES (KSTEPS * 4 * 512)   // 34816 (fragment-direct layout)
#define TAU   5e-3f              // rescore window (fp16 err + enc quantization)
#define HCTA  (2 * ((VOCAB + MT - 1) / MT))   // 1564

// smem layout (argmin kernel)
#define SO_BAR  0                // mbarriers: bfull[2]@0,8  cons[2]@16,24
#define SO_MAP  64               // 128 ints
#define SO_B    1024             // 2 x 34816 B buffers (A staged here first)
#define SMEM_TOTAL (SO_B + 2 * TILE_BYTES)   // 70656

__device__ float  g_cnorm[KCODE];
__device__ int    g_mark[VOCAB];
__device__ int    g_uniq[VOCAB];
__device__ int    g_nuniq;
__device__ unsigned long long g_c0enc = 0xFFFFFFFFFFFFFFFFull;  // (distbits<<32)|idx
__device__ int    g_ridx[VOCAB];
__device__ uint4  g_rencH[2 * VOCAB];    // per-half top-4 packed (dist|code) encs
__device__ __align__(16) unsigned char g_btiles[NTT * TILE_BYTES];  // ~1.1MB

// ---------------------------------------------------------------- PTX helpers
__device__ __forceinline__ uint32_t smem_u32(const void* p) {
    uint32_t a;
    asm("{ .reg .u64 t; cvta.to.shared.u64 t, %1; cvt.u32.u64 %0, t; }" : "=r"(a) : "l"(p));
    return a;
}
#define MBAR_INIT(a, n) asm volatile("mbarrier.init.shared.b64 [%0], %1;" :: "r"(a), "r"(n) : "memory")
#define MBAR_EXPECT_TX(a, b) asm volatile("mbarrier.arrive.expect_tx.shared.b64 _, [%0], %1;" :: "r"(a), "r"(b) : "memory")
#define MBAR_ARRIVE(a) asm volatile("mbarrier.arrive.shared.b64 _, [%0];" :: "r"(a) : "memory")
#define MBAR_WAIT(a, p) do {                                                   \
    asm volatile("{\n\t.reg .pred P1;\n\tWL%=:\n\t"                            \
        "mbarrier.try_wait.parity.acquire.cta.shared::cta.b64 P1, [%0], %1, 0x989680;\n\t" \
        "@P1 bra.uni WD%=;\n\tbra.uni WL%=;\n\tWD%=:\n\t}"                     \
        :: "r"(a), "r"(p) : "memory");                                         \
} while (0)
#define BULK_G2S(dst, src, bytes, mbar)                                        \
    asm volatile("cp.async.bulk.shared::cta.global.mbarrier::complete_tx::bytes [%0], [%1], %2, [%3];" \
                 :: "r"(dst), "l"(src), "r"(bytes), "r"(mbar) : "memory")

#define LDSM_X4(r, a)                                                          \
    asm volatile("ldmatrix.sync.aligned.m8n8.x4.shared.b16 {%0,%1,%2,%3}, [%4];" \
        : "=r"((r)[0]), "=r"((r)[1]), "=r"((r)[2]), "=r"((r)[3]) : "r"(a))
#define LDS128(r, a)                                                           \
    asm volatile("ld.shared.v4.b32 {%0,%1,%2,%3}, [%4];"                       \
        : "=r"((r)[0]), "=r"((r)[1]), "=r"((r)[2]), "=r"((r)[3]) : "r"(a))

__device__ __forceinline__ void mma_f16(float* d, const unsigned* a, const unsigned* b) {
    asm volatile("mma.sync.aligned.m16n8k16.row.col.f32.f16.f16.f32 "
        "{%0,%1,%2,%3}, {%4,%5,%6,%7}, {%8,%9}, {%0,%1,%2,%3};"
        : "+f"(d[0]), "+f"(d[1]), "+f"(d[2]), "+f"(d[3])
        : "r"(a[0]), "r"(a[1]), "r"(a[2]), "r"(a[3]), "r"(b[0]), "r"(b[1]));
}
__device__ __forceinline__ void mma_f16_z(float* d, const unsigned* a, const unsigned* b) {
    asm volatile("mma.sync.aligned.m16n8k16.row.col.f32.f16.f16.f32 "
        "{%0,%1,%2,%3}, {%4,%5,%6,%7}, {%8,%9}, {%10,%10,%10,%10};"
        : "=f"(d[0]), "=f"(d[1]), "=f"(d[2]), "=f"(d[3])
        : "r"(a[0]), "r"(a[1]), "r"(a[2]), "r"(a[3]), "r"(b[0]), "r"(b[1]),
          "f"(0.0f));
}
__device__ __forceinline__ unsigned packh(float a, float b) {
    __half2 h = __floats2half2_rn(a, b);
    return *reinterpret_cast<unsigned*>(&h);
}
// fp32 bits -> monotonic unsigned key (handles negatives)
__device__ __forceinline__ unsigned fkey(float f) {
    unsigned b = __float_as_uint(f);
    return b ^ ((unsigned)(((int)b) >> 31) | 0x80000000u);
}
// inverse of fkey (code bits in low 11 are noise <= ~5e-4 on the dist)
__device__ __forceinline__ float fdec(unsigned k) {
    unsigned b = k ^ ((unsigned)(((int)(~k)) >> 31) | 0x80000000u);
    return __uint_as_float(b);
}
// sorted-insert into ascending packed top-4
__device__ __forceinline__ void ins4u(unsigned d, unsigned t[4]) {
#pragma unroll
    for (int q = 0; q < 4; q++) {
        bool lt = d < t[q];
        unsigned nt = lt ? d : t[q];
        d = lt ? t[q] : d;
        t[q] = nt;
    }
}

// ---------------------------------------------------------------- kernel 1: ||c||^2 + global argmin (c0)
__global__ void cnorm_kernel(const float* __restrict__ cb) {
    int code = blockIdx.x * 8 + (threadIdx.x >> 5);
    int lane = threadIdx.x & 31;
    const float4* p = (const float4*)(cb + (size_t)code * DIMN);
    float s = 0.f;
#pragma unroll
    for (int i = 0; i < 2; i++) {
        float4 v = p[lane + 32 * i];
        s += v.x * v.x + v.y * v.y + v.z * v.z + v.w * v.w;
    }
#pragma unroll
    for (int o = 16; o; o >>= 1) s += __shfl_xor_sync(0xffffffffu, s, o);
    if (lane == 0) {
        g_cnorm[code] = s;
        unsigned long long enc = ((unsigned long long)__float_as_uint(s) << 32)
                               | (unsigned)code;
        atomicMin(&g_c0enc, enc);   // idempotent across graph replays
    }
}

// ---------------------------------------------------------------- kernel 2: fragment-direct fp16 tiles
__global__ void bsplit_kernel(const float* __restrict__ cb) {
    int gid = blockIdx.x * blockDim.x + threadIdx.x;   // 0 .. 278527
    if (gid < VOCAB) g_mark[gid] = 0;
    if (gid == 0) g_nuniq = 0;
    int tile = gid / (KSTEPS * 4 * 128);
    int rem  = gid % (KSTEPS * 4 * 128);
    int idx = rem >> 7;
    int li  = (rem >> 2) & 31;
    int r   = rem & 3;
    int ks  = idx >> 2, jp = idx & 3;
    int n  = tile * 64 + jp * 16 + ((r & 2) ? 8 : 0) + (li >> 2);
    int kk = ks * 16 + (li & 3) * 2 + ((r & 1) ? 8 : 0);
    unsigned val;
    if (ks < 16) {
        val = packh(cb[(size_t)n * DIMN + kk], cb[(size_t)n * DIMN + kk + 1]);
    } else if (((li & 3) == 0) && !(r & 1)) {   // dims 256,257 only
        float cn = g_cnorm[n];
        __half hi = __float2half_rn(cn);
        __half lo = __float2half_rn(cn - __half2float(hi));
        val = (unsigned)__half_as_ushort(hi) | ((unsigned)__half_as_ushort(lo) << 16);
    } else val = 0u;
    *(unsigned*)(g_btiles + (size_t)tile * TILE_BYTES
                 + (uint32_t)idx * 512u + (uint32_t)li * 16u + (uint32_t)r * 4u) = val;
}

// ---------------------------------------------------------------- kernel 3: collect unique valid ids
__global__ void compact_kernel(const int* __restrict__ ids, const int* __restrict__ msk) {
    int r = blockIdx.x * blockDim.x + threadIdx.x;
    if (r >= NROWS) return;
    if (msk[r] >= 1) {
        int id = ids[r];
        if (atomicExch(&g_mark[id], 1) == 0) {
            int pos = atomicAdd(&g_nuniq, 1);
            g_uniq[pos] = id;
        }
    }
}

// ---------------------------------------------------------------- kernel 4: fp16 HMMA argmin
// Packed-u32 top-4 epilogue: pack (sign-folded dist | code) -> min-tree -> rare insert.
__global__ void __launch_bounds__(256, 2)
argmin_mma(const float* __restrict__ emb)
{
    extern __shared__ char smem[];
    const uint32_t sb  = smem_u32(smem);
    const int tid = threadIdx.x;
    const int l   = tid & 31;
    const int w   = tid >> 5;
    const int ublk = blockIdx.x >> 1;
    const int half = blockIdx.x & 1;
    const int r0   = ublk * MT;
    const int nuniq = g_nuniq;
    if (r0 >= nuniq) return;
    const int t0 = half * NTH;
    int* s_map = (int*)(smem + SO_MAP);

    const uint32_t mb_bfull = sb + SO_BAR;
    const uint32_t mb_cons  = sb + SO_BAR + 16;

    if (tid == 0) {
        MBAR_INIT(mb_bfull + 0, 1); MBAR_INIT(mb_bfull + 8, 1);
        MBAR_INIT(mb_cons + 0, 8);  MBAR_INIT(mb_cons + 8, 8);
    }

    // ---- stage A = -2e (fp16) into B region temporarily (ldmatrix layout)
    {
        const int row  = tid >> 1, hf = tid & 1;
        int u = r0 + row; if (u >= nuniq) u = nuniq - 1;
        const int id = g_uniq[u];
        if (hf == 0) s_map[row] = id;
        const float4* ep = (const float4*)(emb + (size_t)id * DIMN + hf * 128);
        const uint32_t rowbase = (uint32_t)row * 512u;
        const uint32_t hb = (uint32_t)hf * 256u;
        const uint32_t xo = (uint32_t)(row & 7) << 4;
#pragma unroll
        for (int q = 0; q < 32; q++) {
            float4 v = ep[q];
            uint32_t off = rowbase + ((hb + (uint32_t)q * 8u) ^ xo);
            *(unsigned*)(smem + SO_B + off)     = packh(-2.f * v.x, -2.f * v.y);
            *(unsigned*)(smem + SO_B + off + 4) = packh(-2.f * v.z, -2.f * v.w);
        }
    }
    __syncthreads();

    const uint32_t xorv   = (uint32_t)(l & 7) << 4;
    const uint32_t arow   = (uint32_t)(w * 16 + (l & 7) + ((l >> 3) & 1) * 8);
    const uint32_t koff_a = (uint32_t)((l >> 4) & 1) * 16u;

    // ---- A fragments -> persistent registers (64 regs)
    unsigned ah[16][4];
    {
        const uint32_t a_b = sb + SO_B + arow * 512u;
#pragma unroll
        for (int s = 0; s < 16; s++)
            LDSM_X4(ah[s], a_b + (((uint32_t)(s * 32) + koff_a) ^ xorv));
    }
    unsigned ah16[4];
    ah16[0] = ah16[1] = ((l & 3) == 0) ? 0x3C003C00u : 0u;
    ah16[2] = ah16[3] = 0u;
    __syncthreads();   // staging region free -> B double buffer

    if (tid == 0) {
        MBAR_EXPECT_TX(mb_bfull + 0, TILE_BYTES);
        BULK_G2S(sb + SO_B, (const void*)(g_btiles + (size_t)t0 * TILE_BYTES),
                 TILE_BYTES, mb_bfull + 0);
        MBAR_EXPECT_TX(mb_bfull + 8, TILE_BYTES);
        BULK_G2S(sb + SO_B + TILE_BYTES,
                 (const void*)(g_btiles + (size_t)(t0 + 1) * TILE_BYTES),
                 TILE_BYTES, mb_bfull + 8);
    }

    unsigned top[2][4];
#pragma unroll
    for (int rr = 0; rr < 2; rr++)
#pragma unroll
        for (int q = 0; q < 4; q++) top[rr][q] = 0xFFFFFFFFu;

    int bpar[2] = {0, 0}, cpar[2] = {0, 0};
    const int cb_l = 2 * (l & 3);

    for (int t = 0; t < NTH; t++) {
        const int buf = t & 1;
        const uint32_t Rb = sb + SO_B + (uint32_t)buf * TILE_BYTES + (uint32_t)l * 16u;
        MBAR_WAIT(mb_bfull + 8 * buf, (uint32_t)bpar[buf]); bpar[buf] ^= 1;

#pragma unroll
        for (int p = 0; p < 2; p++) {
            const uint32_t Rbp = Rb + (uint32_t)p * 1024u;
            float acc[4][4];
            unsigned b4[4][4];
            LDS128(b4[0], Rbp);
            LDS128(b4[1], Rbp + 512u);
            LDS128(b4[2], Rbp + 2048u);
            LDS128(b4[3], Rbp + 2560u);
#pragma unroll
            for (int ii = 0; ii < 34; ii++) {
                const int cur = ii & 3;
                const int ks  = ii >> 1;
                const int jl  = ii & 1;
                const unsigned* af = (ks == 16) ? ah16 : ah[ks];
                if (ii < 2) {
                    mma_f16_z(acc[2 * jl],     af, b4[cur]);
                    mma_f16_z(acc[2 * jl + 1], af, b4[cur] + 2);
                } else {
                    mma_f16(acc[2 * jl],     af, b4[cur]);
                    mma_f16(acc[2 * jl + 1], af, b4[cur] + 2);
                }
                if (ii + 4 < 34) {
                    const uint32_t noff = (uint32_t)(((ii + 4) >> 1) * 2048 + ((ii + 4) & 1) * 512);
                    LDS128(b4[cur], Rbp + noff);
                }
            }

            // ---- packed epilogue: 3 ALU/elem pack, 7-IMNMX min-tree, rare insert
            const unsigned cbase = (unsigned)((t0 + t) * NTIL + p * 32 + cb_l);
            unsigned enc[2][8];
#pragma unroll
            for (int j = 0; j < 4; j++) {
#pragma unroll
                for (int e = 0; e < 4; e++) {
                    const int rr = e >> 1;
                    const unsigned code = cbase + (unsigned)((j >> 1) * 16 + (j & 1) * 8 + (e & 1));
                    enc[rr][j * 2 + (e & 1)] = (fkey(acc[j][e]) & 0xFFFFF800u) | code;
                }
            }
#pragma unroll
            for (int rr = 0; rr < 2; rr++) {
                unsigned m = enc[rr][0];
#pragma unroll
                for (int q = 1; q < 8; q++) m = umin(m, enc[rr][q]);
                if (m < top[rr][3]) {
#pragma unroll 1
                    for (int q = 0; q < 8; q++)
                        if (enc[rr][q] < top[rr][3]) ins4u(enc[rr][q], top[rr]);
                }
            }
        }
        if (l == 0) MBAR_ARRIVE(mb_cons + 8 * buf);

        if (tid == 0 && t + 2 < NTH) {
            MBAR_WAIT(mb_cons + 8 * buf, (uint32_t)cpar[buf]); cpar[buf] ^= 1;
            MBAR_EXPECT_TX(mb_bfull + 8 * buf, TILE_BYTES);
            BULK_G2S(sb + SO_B + (uint32_t)buf * TILE_BYTES,
                     (const void*)(g_btiles + (size_t)(t0 + t + 2) * TILE_BYTES),
                     TILE_BYTES, mb_bfull + 8 * buf);
        }
    }

    // ---- merge packed top-4 across the 4 lanes sharing each row
#pragma unroll
    for (int rr = 0; rr < 2; rr++) {
#pragma unroll
        for (int off = 1; off <= 2; off <<= 1) {
            unsigned ov[4];
#pragma unroll
            for (int q = 0; q < 4; q++)
                ov[q] = __shfl_xor_sync(0xffffffffu, top[rr][q], off);
#pragma unroll
            for (int q = 0; q < 4; q++) ins4u(ov[q], top[rr]);
        }
        if ((l & 3) == 0) {
            const int id = s_map[w * 16 + (l >> 2) + rr * 8];
            g_rencH[half * VOCAB + id] =
                make_uint4(top[rr][0], top[rr][1], top[rr][2], top[rr][3]);
        }
    }
}

// ---------------------------------------------------------------- kernel 5: merge halves + exact rescore
__global__ void rescore_kernel(const float* __restrict__ emb, const float* __restrict__ cb)
{
    int u = blockIdx.x * blockDim.x + threadIdx.x;
    if (u >= g_nuniq) return;
    const int id = g_uniq[u];
    uint4 ea = g_rencH[id];
    uint4 eb = g_rencH[VOCAB + id];
    unsigned t[4] = {ea.x, ea.y, ea.z, ea.w};
    ins4u(eb.x, t); ins4u(eb.y, t); ins4u(eb.z, t); ins4u(eb.w, t);

    if (fdec(t[1]) - fdec(t[0]) >= TAU) { g_ridx[id] = (int)(t[0] & 2047u); return; }

    const float* e = emb + (size_t)id * DIMN;
    float bestd = 3.4e38f; int besti = 0x7fffffff;
#pragma unroll
    for (int q = 0; q < 4; q++) {
        const int c = (int)(t[q] & 2047u);
        const float* cp = cb + (size_t)c * DIMN;
        float a = 0.f, b = 0.f;
#pragma unroll 4
        for (int k = 0; k < DIMN; k += 2) {
            a = fmaf(e[k],     cp[k],     a);
            b = fmaf(e[k + 1], cp[k + 1], b);
        }
        float d = fmaf(-2.0f, a + b, g_cnorm[c]);
        if (d < bestd || (d == bestd && c < besti)) { bestd = d; besti = c; }
    }
    g_ridx[id] = besti;
}

// ---------------------------------------------------------------- kernel 6: means + encoder dense
__global__ void __launch_bounds__(256)
finish_kernel(const int* __restrict__ ids, const int* __restrict__ msk,
              const float* __restrict__ emb, const float* __restrict__ cb,
              const float* __restrict__ W,   const float* __restrict__ bias,
              float* __restrict__ out)
{
    __shared__ int   s_id[LL];
    __shared__ float s_m[LL];
    __shared__ int   s_vq[LL];
    __shared__ float s_x[2 * DIMN];
    __shared__ int   s_cnt;

    const int b = blockIdx.x, tid = threadIdx.x;
    if (tid == 0) s_cnt = 0;
    __syncthreads();
    const int c0 = (int)(unsigned)(g_c0enc & 0xFFFFFFFFull);
    if (tid < LL) {
        int   id = ids[b * LL + tid];
        int   mv = msk[b * LL + tid];
        float m  = (mv >= 1) ? 1.f : 0.f;
        s_id[tid] = id;
        s_m[tid]  = m;
        s_vq[tid] = (mv >= 1) ? g_ridx[id] : c0;
        if (m > 0.f) atomicAdd(&s_cnt, 1);
    }
    __syncthreads();

    const float cnt = (float)s_cnt;
    const int   d   = tid;
    float hist = 0.f, vq = 0.f;
#pragma unroll 4
    for (int ll = 0; ll < LL; ll++) {
        hist = fmaf(emb[(size_t)s_id[ll] * DIMN + d], s_m[ll], hist);
        vq  += cb[(size_t)s_vq[ll] * DIMN + d];
    }
    s_x[d]        = vq / cnt;
    s_x[DIMN + d] = hist / (cnt + 1e-9f);
    __syncthreads();

    float a0 = bias[d], a1 = 0.f;
#pragma unroll 8
    for (int i = 0; i < DIMN; i++) {
        a0 = fmaf(s_x[i],        W[(size_t)i * DIMN + d],          a0);
        a1 = fmaf(s_x[DIMN + i], W[(size_t)(DIMN + i) * DIMN + d], a1);
    }
    out[(size_t)b * DIMN + d] = a0 + a1;
}

// ----------------------------------------------------------------
extern "C" void kernel_launch(void* const* d_in, const int* in_sizes, int n_in,
                              void* d_out, int out_size)
{
    const int*   ids  = (const int*)  d_in[0];
    const int*   msk  = (const int*)  d_in[1];
    const float* emb  = (const float*)d_in[2];
    const float* cb   = (const float*)d_in[3];
    const float* W    = (const float*)d_in[4];
    const float* bias = (const float*)d_in[5];
    float*       out  = (float*)d_out;

    cudaFuncSetAttribute(argmin_mma,
                         cudaFuncAttributeMaxDynamicSharedMemorySize, SMEM_TOTAL);

    cnorm_kernel<<<KCODE / 8, 256>>>(cb);                          // 1 (+ c0 atomicMin)
    bsplit_kernel<<<(NTT * KSTEPS * 4 * 128) / 256, 256>>>(cb);    // 2
    compact_kernel<<<(NROWS + 255) / 256, 256>>>(ids, msk);        // 3
    argmin_mma<<<HCTA, 256, SMEM_TOTAL>>>(emb);                    // 4
    rescore_kernel<<<(VOCAB + 255) / 256, 256>>>(emb, cb);         // 5 (merge+rescore)
    finish_kernel<<<BB, 256>>>(ids, msk, emb, cb, W, bias, out);   // 6
}

// round 11
// speedup vs baseline: 1.3560x; 1.0516x over previous
#include <cuda_runtime.h>
#include <cuda_fp16.h>
#include <cstdint>
#include <cstddef>

// ---------------------------------------------------------------- constants
#define BB    512
#define LL    200
#define DIMN  256
#define KCODE 2048
#define NROWS (BB * LL)          // 102400
#define VOCAB 100000

#define MT    256                // unique ids per CTA (32 rows per warp)
#define NTIL  64                 // codes per tile
#define NTT   32                 // total tiles
#define NTH   16                 // tiles per half-CTA
#define KSTEPS 17                // 16 data k-steps + 1 cnorm k-step
#define TILE_BYTES (KSTEPS * 4 * 512)   // 34816 (fragment-direct layout)
#define TAU   5e-3f              // rescore window (fp16 err + enc quantization)
#define HCTA  (2 * ((VOCAB + MT - 1) / MT))   // 782

// smem layout (argmin kernel)
#define SO_BAR  0                // mbarriers: bfull[2]@0,8  cons[2]@16,24
#define SO_MAP  64               // 256 ints (unique-id slice)
#define SO_B    2048             // 2 x 34816 B buffers (A staged here first)
#define SMEM_TOTAL (SO_B + 2 * TILE_BYTES)   // 71680

__device__ float  g_cnorm[KCODE];
__device__ int    g_mark[VOCAB];
__device__ int    g_uniq[VOCAB];
__device__ int    g_nuniq;
__device__ unsigned long long g_c0enc = 0xFFFFFFFFFFFFFFFFull;  // (distbits<<32)|idx
__device__ int    g_ridx[VOCAB];
__device__ uint4  g_rencH[2 * VOCAB];    // per-half top-4 packed (dist|code) encs
__device__ __align__(16) unsigned char g_btiles[NTT * TILE_BYTES];  // ~1.1MB

// ---------------------------------------------------------------- PTX helpers
__device__ __forceinline__ uint32_t smem_u32(const void* p) {
    uint32_t a;
    asm("{ .reg .u64 t; cvta.to.shared.u64 t, %1; cvt.u32.u64 %0, t; }" : "=r"(a) : "l"(p));
    return a;
}
#define MBAR_INIT(a, n) asm volatile("mbarrier.init.shared.b64 [%0], %1;" :: "r"(a), "r"(n) : "memory")
#define MBAR_EXPECT_TX(a, b) asm volatile("mbarrier.arrive.expect_tx.shared.b64 _, [%0], %1;" :: "r"(a), "r"(b) : "memory")
#define MBAR_ARRIVE(a) asm volatile("mbarrier.arrive.shared.b64 _, [%0];" :: "r"(a) : "memory")
#define MBAR_WAIT(a, p) do {                                                   \
    asm volatile("{\n\t.reg .pred P1;\n\tWL%=:\n\t"                            \
        "mbarrier.try_wait.parity.acquire.cta.shared::cta.b64 P1, [%0], %1, 0x989680;\n\t" \
        "@P1 bra.uni WD%=;\n\tbra.uni WL%=;\n\tWD%=:\n\t}"                     \
        :: "r"(a), "r"(p) : "memory");                                         \
} while (0)
#define BULK_G2S(dst, src, bytes, mbar)                                        \
    asm volatile("cp.async.bulk.shared::cta.global.mbarrier::complete_tx::bytes [%0], [%1], %2, [%3];" \
                 :: "r"(dst), "l"(src), "r"(bytes), "r"(mbar) : "memory")

#define LDSM_X4(r, a)                                                          \
    asm volatile("ldmatrix.sync.aligned.m8n8.x4.shared.b16 {%0,%1,%2,%3}, [%4];" \
        : "=r"((r)[0]), "=r"((r)[1]), "=r"((r)[2]), "=r"((r)[3]) : "r"(a))
#define LDS128(r, a)                                                           \
    asm volatile("ld.shared.v4.b32 {%0,%1,%2,%3}, [%4];"                       \
        : "=r"((r)[0]), "=r"((r)[1]), "=r"((r)[2]), "=r"((r)[3]) : "r"(a))

__device__ __forceinline__ void mma_f16(float* d, const unsigned* a, const unsigned* b) {
    asm volatile("mma.sync.aligned.m16n8k16.row.col.f32.f16.f16.f32 "
        "{%0,%1,%2,%3}, {%4,%5,%6,%7}, {%8,%9}, {%0,%1,%2,%3};"
        : "+f"(d[0]), "+f"(d[1]), "+f"(d[2]), "+f"(d[3])
        : "r"(a[0]), "r"(a[1]), "r"(a[2]), "r"(a[3]), "r"(b[0]), "r"(b[1]));
}
__device__ __forceinline__ void mma_f16_z(float* d, const unsigned* a, const unsigned* b) {
    asm volatile("mma.sync.aligned.m16n8k16.row.col.f32.f16.f16.f32 "
        "{%0,%1,%2,%3}, {%4,%5,%6,%7}, {%8,%9}, {%10,%10,%10,%10};"
        : "=f"(d[0]), "=f"(d[1]), "=f"(d[2]), "=f"(d[3])
        : "r"(a[0]), "r"(a[1]), "r"(a[2]), "r"(a[3]), "r"(b[0]), "r"(b[1]),
          "f"(0.0f));
}
__device__ __forceinline__ unsigned packh(float a, float b) {
    __half2 h = __floats2half2_rn(a, b);
    return *reinterpret_cast<unsigned*>(&h);
}
// fp32 bits -> monotonic unsigned key (handles negatives)
__device__ __forceinline__ unsigned fkey(float f) {
    unsigned b = __float_as_uint(f);
    return b ^ ((unsigned)(((int)b) >> 31) | 0x80000000u);
}
__device__ __forceinline__ float fdec(unsigned k) {
    unsigned b = k ^ ((unsigned)(((int)(~k)) >> 31) | 0x80000000u);
    return __uint_as_float(b);
}
// sorted-insert into ascending packed top-4
__device__ __forceinline__ void ins4u(unsigned d, unsigned t[4]) {
#pragma unroll
    for (int q = 0; q < 4; q++) {
        bool lt = d < t[q];
        unsigned nt = lt ? d : t[q];
        d = lt ? t[q] : d;
        t[q] = nt;
    }
}

// ---------------------------------------------------------------- kernel 1: ||c||^2 + global argmin (c0)
__global__ void cnorm_kernel(const float* __restrict__ cb) {
    int code = blockIdx.x * 8 + (threadIdx.x >> 5);
    int lane = threadIdx.x & 31;
    const float4* p = (const float4*)(cb + (size_t)code * DIMN);
    float s = 0.f;
#pragma unroll
    for (int i = 0; i < 2; i++) {
        float4 v = p[lane + 32 * i];
        s += v.x * v.x + v.y * v.y + v.z * v.z + v.w * v.w;
    }
#pragma unroll
    for (int o = 16; o; o >>= 1) s += __shfl_xor_sync(0xffffffffu, s, o);
    if (lane == 0) {
        g_cnorm[code] = s;
        unsigned long long enc = ((unsigned long long)__float_as_uint(s) << 32)
                               | (unsigned)code;
        atomicMin(&g_c0enc, enc);   // idempotent across graph replays
    }
}

// ---------------------------------------------------------------- kernel 2: fragment-direct fp16 tiles
__global__ void bsplit_kernel(const float* __restrict__ cb) {
    int gid = blockIdx.x * blockDim.x + threadIdx.x;   // 0 .. 278527
    if (gid < VOCAB) g_mark[gid] = 0;
    if (gid == 0) g_nuniq = 0;
    int tile = gid / (KSTEPS * 4 * 128);
    int rem  = gid % (KSTEPS * 4 * 128);
    int idx = rem >> 7;
    int li  = (rem >> 2) & 31;
    int r   = rem & 3;
    int ks  = idx >> 2, jp = idx & 3;
    int n  = tile * 64 + jp * 16 + ((r & 2) ? 8 : 0) + (li >> 2);
    int kk = ks * 16 + (li & 3) * 2 + ((r & 1) ? 8 : 0);
    unsigned val;
    if (ks < 16) {
        val = packh(cb[(size_t)n * DIMN + kk], cb[(size_t)n * DIMN + kk + 1]);
    } else if (((li & 3) == 0) && !(r & 1)) {   // dims 256,257 only
        float cn = g_cnorm[n];
        __half hi = __float2half_rn(cn);
        __half lo = __float2half_rn(cn - __half2float(hi));
        val = (unsigned)__half_as_ushort(hi) | ((unsigned)__half_as_ushort(lo) << 16);
    } else val = 0u;
    *(unsigned*)(g_btiles + (size_t)tile * TILE_BYTES
                 + (uint32_t)idx * 512u + (uint32_t)li * 16u + (uint32_t)r * 4u) = val;
}

// ---------------------------------------------------------------- kernel 3: collect unique valid ids
__global__ void compact_kernel(const int* __restrict__ ids, const int* __restrict__ msk) {
    int r = blockIdx.x * blockDim.x + threadIdx.x;
    if (r >= NROWS) return;
    if (msk[r] >= 1) {
        int id = ids[r];
        if (atomicExch(&g_mark[id], 1) == 0) {
            int pos = atomicAdd(&g_nuniq, 1);
            g_uniq[pos] = id;
        }
    }
}

// ---------------------------------------------------------------- kernel 4: fp16 HMMA argmin
// M=32 per warp (2 row-blocks): each B fragment feeds 4 mmas -> smem traffic/MAC halved.
__global__ void __launch_bounds__(256, 1)
argmin_mma(const float* __restrict__ emb)
{
    extern __shared__ char smem[];
    const uint32_t sb  = smem_u32(smem);
    const int tid = threadIdx.x;
    const int l   = tid & 31;
    const int w   = tid >> 5;
    const int ublk = blockIdx.x >> 1;
    const int half = blockIdx.x & 1;
    const int r0   = ublk * MT;
    const int nuniq = g_nuniq;
    if (r0 >= nuniq) return;
    const int t0 = half * NTH;
    int* s_map = (int*)(smem + SO_MAP);

    const uint32_t mb_bfull = sb + SO_BAR;
    const uint32_t mb_cons  = sb + SO_BAR + 16;

    if (tid == 0) {
        MBAR_INIT(mb_bfull + 0, 1); MBAR_INIT(mb_bfull + 8, 1);
        MBAR_INIT(mb_cons + 0, 8);  MBAR_INIT(mb_cons + 8, 8);
    }

    const uint32_t xorv   = (uint32_t)(l & 7) << 4;
    const uint32_t koff_a = (uint32_t)((l >> 4) & 1) * 16u;

    // ---- stage A = -2e (fp16) in two 128-row batches; load frags per batch
    unsigned ah2[2][16][4];      // [row-block][k-step][frag]
#pragma unroll 1
    for (int batch = 0; batch < 2; batch++) {
        const int row = tid >> 1, hf = tid & 1;
        int u = r0 + batch * 128 + row;
        if (u >= nuniq) u = nuniq - 1;        // tail duplicates
        const int id = g_uniq[u];
        if (hf == 0) s_map[batch * 128 + row] = id;
        const float4* ep = (const float4*)(emb + (size_t)id * DIMN + hf * 128);
        const uint32_t rowbase = (uint32_t)row * 512u;
        const uint32_t hb = (uint32_t)hf * 256u;
        const uint32_t xo = (uint32_t)(row & 7) << 4;
#pragma unroll
        for (int q = 0; q < 32; q++) {
            float4 v = ep[q];
            uint32_t off = rowbase + ((hb + (uint32_t)q * 8u) ^ xo);
            *(unsigned*)(smem + SO_B + off)     = packh(-2.f * v.x, -2.f * v.y);
            *(unsigned*)(smem + SO_B + off + 4) = packh(-2.f * v.z, -2.f * v.w);
        }
        __syncthreads();
        if ((w >> 2) == batch) {
#pragma unroll
            for (int rb = 0; rb < 2; rb++) {
                const uint32_t arow = (uint32_t)((w & 3) * 32 + rb * 16 + (l & 7) + ((l >> 3) & 1) * 8);
                const uint32_t a_b = sb + SO_B + arow * 512u;
#pragma unroll
                for (int s = 0; s < 16; s++)
                    LDSM_X4(ah2[rb][s], a_b + (((uint32_t)(s * 32) + koff_a) ^ xorv));
            }
        }
        __syncthreads();
    }
    // cnorm k-step A fragment (constant: dims 256,257 = 1)
    unsigned ah16[4];
    ah16[0] = ah16[1] = ((l & 3) == 0) ? 0x3C003C00u : 0u;
    ah16[2] = ah16[3] = 0u;

    if (tid == 0) {
        MBAR_EXPECT_TX(mb_bfull + 0, TILE_BYTES);
        BULK_G2S(sb + SO_B, (const void*)(g_btiles + (size_t)t0 * TILE_BYTES),
                 TILE_BYTES, mb_bfull + 0);
        MBAR_EXPECT_TX(mb_bfull + 8, TILE_BYTES);
        BULK_G2S(sb + SO_B + TILE_BYTES,
                 (const void*)(g_btiles + (size_t)(t0 + 1) * TILE_BYTES),
                 TILE_BYTES, mb_bfull + 8);
    }

    unsigned top[4][4];          // groups: g = rb*2 + eh
#pragma unroll
    for (int g = 0; g < 4; g++)
#pragma unroll
        for (int q = 0; q < 4; q++) top[g][q] = 0xFFFFFFFFu;

    int bpar[2] = {0, 0}, cpar[2] = {0, 0};
    const unsigned cb_l = 2u * (unsigned)(l & 3);

    for (int t = 0; t < NTH; t++) {
        const int buf = t & 1;
        const uint32_t Rb = sb + SO_B + (uint32_t)buf * TILE_BYTES + (uint32_t)l * 16u;
        MBAR_WAIT(mb_bfull + 8 * buf, (uint32_t)bpar[buf]); bpar[buf] ^= 1;

#pragma unroll
        for (int q = 0; q < 4; q++) {     // quarter = 16 codes
            const uint32_t Rbq = Rb + (uint32_t)q * 512u;
            float acc[2][2][4];
            unsigned b4[4][4];
            LDS128(b4[0], Rbq);
            LDS128(b4[1], Rbq + 2048u);
            LDS128(b4[2], Rbq + 4096u);
            LDS128(b4[3], Rbq + 6144u);
#pragma unroll
            for (int ks = 0; ks < KSTEPS; ks++) {
                const int cur = ks & 3;
                const unsigned* alo = (ks == 16) ? ah16 : ah2[0][ks];
                const unsigned* ahi = (ks == 16) ? ah16 : ah2[1][ks];
                if (ks == 0) {
                    mma_f16_z(acc[0][0], alo, b4[cur]);
                    mma_f16_z(acc[0][1], alo, b4[cur] + 2);
                    mma_f16_z(acc[1][0], ahi, b4[cur]);
                    mma_f16_z(acc[1][1], ahi, b4[cur] + 2);
                } else {
                    mma_f16(acc[0][0], alo, b4[cur]);
                    mma_f16(acc[0][1], alo, b4[cur] + 2);
                    mma_f16(acc[1][0], ahi, b4[cur]);
                    mma_f16(acc[1][1], ahi, b4[cur] + 2);
                }
                if (ks + 4 < KSTEPS) LDS128(b4[cur], Rbq + (uint32_t)(ks + 4) * 2048u);
            }

            // epilogue: static float min-tree, exact u32 insert in rare branch
            const unsigned cc = (unsigned)((t0 + t) * NTIL + q * 16) + cb_l;
#pragma unroll
            for (int rb = 0; rb < 2; rb++) {
#pragma unroll
                for (int eh = 0; eh < 2; eh++) {
                    const int g = rb * 2 + eh;
                    float m = fminf(fminf(acc[rb][0][2 * eh], acc[rb][0][2 * eh + 1]),
                                    fminf(acc[rb][1][2 * eh], acc[rb][1][2 * eh + 1]));
                    unsigned mk = fkey(m) & 0xFFFFF800u;
                    if (mk < top[g][3]) {
                        unsigned e0 = (fkey(acc[rb][0][2 * eh    ]) & 0xFFFFF800u) | (cc + 0u);
                        unsigned e1 = (fkey(acc[rb][0][2 * eh + 1]) & 0xFFFFF800u) | (cc + 1u);
                        unsigned e2 = (fkey(acc[rb][1][2 * eh    ]) & 0xFFFFF800u) | (cc + 8u);
                        unsigned e3 = (fkey(acc[rb][1][2 * eh + 1]) & 0xFFFFF800u) | (cc + 9u);
                        ins4u(e0, top[g]); ins4u(e1, top[g]);
                        ins4u(e2, top[g]); ins4u(e3, top[g]);
                    }
                }
            }
        }
        if (l == 0) MBAR_ARRIVE(mb_cons + 8 * buf);

        if (tid == 0 && t + 2 < NTH) {
            MBAR_WAIT(mb_cons + 8 * buf, (uint32_t)cpar[buf]); cpar[buf] ^= 1;
            MBAR_EXPECT_TX(mb_bfull + 8 * buf, TILE_BYTES);
            BULK_G2S(sb + SO_B + (uint32_t)buf * TILE_BYTES,
                     (const void*)(g_btiles + (size_t)(t0 + t + 2) * TILE_BYTES),
                     TILE_BYTES, mb_bfull + 8 * buf);
        }
    }

    // ---- merge packed top-4 across the 4 lanes sharing each row
#pragma unroll
    for (int g = 0; g < 4; g++) {
#pragma unroll
        for (int off = 1; off <= 2; off <<= 1) {
            unsigned ov[4];
#pragma unroll
            for (int q = 0; q < 4; q++)
                ov[q] = __shfl_xor_sync(0xffffffffu, top[g][q], off);
#pragma unroll
            for (int q = 0; q < 4; q++) ins4u(ov[q], top[g]);
        }
        if ((l & 3) == 0) {
            const int rb = g >> 1, eh = g & 1;
            const int id = s_map[w * 32 + rb * 16 + (l >> 2) + 8 * eh];
            g_rencH[half * VOCAB + id] =
                make_uint4(top[g][0], top[g][1], top[g][2], top[g][3]);
        }
    }
}

// ---------------------------------------------------------------- kernel 5: merge halves + exact rescore
__global__ void rescore_kernel(const float* __restrict__ emb, const float* __restrict__ cb)
{
    int u = blockIdx.x * blockDim.x + threadIdx.x;
    if (u >= g_nuniq) return;
    const int id = g_uniq[u];
    uint4 ea = g_rencH[id];
    uint4 eb = g_rencH[VOCAB + id];
    unsigned t[4] = {ea.x, ea.y, ea.z, ea.w};
    ins4u(eb.x, t); ins4u(eb.y, t); ins4u(eb.z, t); ins4u(eb.w, t);

    if (fdec(t[1]) - fdec(t[0]) >= TAU) { g_ridx[id] = (int)(t[0] & 2047u); return; }

    const float* e = emb + (size_t)id * DIMN;
    float bestd = 3.4e38f; int besti = 0x7fffffff;
#pragma unroll
    for (int q = 0; q < 4; q++) {
        const int c = (int)(t[q] & 2047u);
        const float* cp = cb + (size_t)c * DIMN;
        float a = 0.f, b = 0.f;
#pragma unroll 4
        for (int k = 0; k < DIMN; k += 2) {
            a = fmaf(e[k],     cp[k],     a);
            b = fmaf(e[k + 1], cp[k + 1], b);
        }
        float d = fmaf(-2.0f, a + b, g_cnorm[c]);
        if (d < bestd || (d == bestd && c < besti)) { bestd = d; besti = c; }
    }
    g_ridx[id] = besti;
}

// ---------------------------------------------------------------- kernel 6: means + encoder dense
__global__ void __launch_bounds__(256)
finish_kernel(const int* __restrict__ ids, const int* __restrict__ msk,
              const float* __restrict__ emb, const float* __restrict__ cb,
              const float* __restrict__ W,   const float* __restrict__ bias,
              float* __restrict__ out)
{
    __shared__ int   s_id[LL];
    __shared__ float s_m[LL];
    __shared__ int   s_vq[LL];
    __shared__ float s_x[2 * DIMN];
    __shared__ int   s_cnt;

    const int b = blockIdx.x, tid = threadIdx.x;
    if (tid == 0) s_cnt = 0;
    __syncthreads();
    const int c0 = (int)(unsigned)(g_c0enc & 0xFFFFFFFFull);
    if (tid < LL) {
        int   id = ids[b * LL + tid];
        int   mv = msk[b * LL + tid];
        float m  = (mv >= 1) ? 1.f : 0.f;
        s_id[tid] = id;
        s_m[tid]  = m;
        s_vq[tid] = (mv >= 1) ? g_ridx[id] : c0;
        if (m > 0.f) atomicAdd(&s_cnt, 1);
    }
    __syncthreads();

    const float cnt = (float)s_cnt;
    const int   d   = tid;
    float hist = 0.f, vq = 0.f;
#pragma unroll 4
    for (int ll = 0; ll < LL; ll++) {
        hist = fmaf(emb[(size_t)s_id[ll] * DIMN + d], s_m[ll], hist);
        vq  += cb[(size_t)s_vq[ll] * DIMN + d];
    }
    s_x[d]        = vq / cnt;
    s_x[DIMN + d] = hist / (cnt + 1e-9f);
    __syncthreads();

    float a0 = bias[d], a1 = 0.f;
#pragma unroll 8
    for (int i = 0; i < DIMN; i++) {
        a0 = fmaf(s_x[i],        W[(size_t)i * DIMN + d],          a0);
        a1 = fmaf(s_x[DIMN + i], W[(size_t)(DIMN + i) * DIMN + d], a1);
    }
    out[(size_t)b * DIMN + d] = a0 + a1;
}

// ----------------------------------------------------------------
extern "C" void kernel_launch(void* const* d_in, const int* in_sizes, int n_in,
                              void* d_out, int out_size)
{
    const int*   ids  = (const int*)  d_in[0];
    const int*   msk  = (const int*)  d_in[1];
    const float* emb  = (const float*)d_in[2];
    const float* cb   = (const float*)d_in[3];
    const float* W    = (const float*)d_in[4];
    const float* bias = (const float*)d_in[5];
    float*       out  = (float*)d_out;

    cudaFuncSetAttribute(argmin_mma,
                         cudaFuncAttributeMaxDynamicSharedMemorySize, SMEM_TOTAL);

    cnorm_kernel<<<KCODE / 8, 256>>>(cb);                          // 1 (+ c0 atomicMin)
    bsplit_kernel<<<(NTT * KSTEPS * 4 * 128) / 256, 256>>>(cb);    // 2
    compact_kernel<<<(NROWS + 255) / 256, 256>>>(ids, msk);        // 3
    argmin_mma<<<HCTA, 256, SMEM_TOTAL>>>(emb);                    // 4
    rescore_kernel<<<(VOCAB + 255) / 256, 256>>>(emb, cb);         // 5 (merge+rescore)
    finish_kernel<<<BB, 256>>>(ids, msk, emb, cb, W, bias, out);   // 6
}